// round 7
// baseline (speedup 1.0000x reference)
#include <cuda_runtime.h>
#include <math.h>

#define NODES 20000

typedef unsigned long long ull;

__device__ float g_qkt[(size_t)NODES * 512];
__device__ float g_u[(size_t)NODES * 512];

__device__ __forceinline__ ull pk2(float x) {
    unsigned xi = __float_as_uint(x);
    ull r;
    asm("mov.b64 %0, {%1, %1};" : "=l"(r) : "r"(xi), "r"(xi));
    return r;
}
__device__ __forceinline__ ull ffma2(ull a, ull b, ull c) {
    ull d;
    asm("fma.rn.f32x2 %0, %1, %2, %3;" : "=l"(d) : "l"(a), "l"(b), "l"(c));
    return d;
}
__device__ __forceinline__ void upk(ull v, float& lo, float& hi) {
    unsigned a, b;
    asm("mov.b64 {%0, %1}, %2;" : "=r"(a), "=r"(b) : "l"(v));
    lo = __uint_as_float(a); hi = __uint_as_float(b);
}

// ---------------------------------------------------------------------------
// K1: q = query@Wq + bq;  qkt[n,h,g] = scale * sum_d q[h,d] * Wk[g, h*32+d]
// ---------------------------------------------------------------------------
__global__ __launch_bounds__(256) void k1_kernel(
    const float* __restrict__ query, const float* __restrict__ Wq,
    const float* __restrict__ bq, const float* __restrict__ Wk)
{
    extern __shared__ float sm[];
    float* buf0 = sm;          // 16384: Wq, then Wk^T
    float* buf1 = sm + 16384;  // 4608: A^T, then Q^T (stride 36)

    const int t = threadIdx.x;
    const int n0 = blockIdx.x * 32;
    const int lane = t & 31, wg = t >> 5;
    const int c0 = 4 * lane, r0 = 4 * wg;

    { const float4* s = (const float4*)Wq; float4* d = (float4*)buf0;
#pragma unroll
      for (int i = 0; i < 16; i++) d[t + 256 * i] = s[t + 256 * i]; }
#pragma unroll
    for (int q = 0; q < 4; q++) {
        int jj = wg * 4 + q;
        float4 v = *(const float4*)(query + (size_t)(n0 + lane) * 128 + 4 * jj);
        buf1[(4 * jj + 0) * 36 + lane] = v.x; buf1[(4 * jj + 1) * 36 + lane] = v.y;
        buf1[(4 * jj + 2) * 36 + lane] = v.z; buf1[(4 * jj + 3) * 36 + lane] = v.w;
    }
    __syncthreads();

    // stage A: Q = A @ Wq + bq
    ull acc[4][2];
#pragma unroll
    for (int i = 0; i < 4; i++) { acc[i][0] = 0ull; acc[i][1] = 0ull; }
#pragma unroll 4
    for (int k = 0; k < 128; k++) {
        float4 a = *(const float4*)(buf1 + k * 36 + r0);
        ulonglong2 b = *(const ulonglong2*)(buf0 + k * 128 + c0);
        ull A;
        A = pk2(a.x); acc[0][0] = ffma2(A, b.x, acc[0][0]); acc[0][1] = ffma2(A, b.y, acc[0][1]);
        A = pk2(a.y); acc[1][0] = ffma2(A, b.x, acc[1][0]); acc[1][1] = ffma2(A, b.y, acc[1][1]);
        A = pk2(a.z); acc[2][0] = ffma2(A, b.x, acc[2][0]); acc[2][1] = ffma2(A, b.y, acc[2][1]);
        A = pk2(a.w); acc[3][0] = ffma2(A, b.x, acc[3][0]); acc[3][1] = ffma2(A, b.y, acc[3][1]);
    }
    float qv[4][4];
    {
        float4 b4 = *(const float4*)(bq + c0);
#pragma unroll
        for (int i = 0; i < 4; i++) {
            upk(acc[i][0], qv[i][0], qv[i][1]); upk(acc[i][1], qv[i][2], qv[i][3]);
            qv[i][0] += b4.x; qv[i][1] += b4.y; qv[i][2] += b4.z; qv[i][3] += b4.w;
        }
    }
    __syncthreads();

    // Q^T into buf1, Wk^T into buf0
#pragma unroll
    for (int i = 0; i < 4; i++)
#pragma unroll
        for (int j = 0; j < 4; j++) buf1[(c0 + j) * 36 + r0 + i] = qv[i][j];
    if (t < 128) {
#pragma unroll 4
        for (int jj = 0; jj < 32; jj++) {
            float4 v = *(const float4*)(Wk + (size_t)t * 128 + 4 * jj);
            buf0[(4 * jj + 0) * 128 + t] = v.x; buf0[(4 * jj + 1) * 128 + t] = v.y;
            buf0[(4 * jj + 2) * 128 + t] = v.z; buf0[(4 * jj + 3) * 128 + t] = v.w;
        }
    }
    __syncthreads();

    // stage B: qkt per head
    const float scale = 0.17677669529663688f;  // 1/sqrt(32)
#pragma unroll
    for (int h = 0; h < 4; h++) {
        ull a2[4][2];
#pragma unroll
        for (int i = 0; i < 4; i++) { a2[i][0] = 0ull; a2[i][1] = 0ull; }
#pragma unroll 4
        for (int d = 0; d < 32; d++) {
            int k2 = h * 32 + d;
            float4 a = *(const float4*)(buf1 + k2 * 36 + r0);
            ulonglong2 b = *(const ulonglong2*)(buf0 + k2 * 128 + c0);
            ull A;
            A = pk2(a.x); a2[0][0] = ffma2(A, b.x, a2[0][0]); a2[0][1] = ffma2(A, b.y, a2[0][1]);
            A = pk2(a.y); a2[1][0] = ffma2(A, b.x, a2[1][0]); a2[1][1] = ffma2(A, b.y, a2[1][1]);
            A = pk2(a.z); a2[2][0] = ffma2(A, b.x, a2[2][0]); a2[2][1] = ffma2(A, b.y, a2[2][1]);
            A = pk2(a.w); a2[3][0] = ffma2(A, b.x, a2[3][0]); a2[3][1] = ffma2(A, b.y, a2[3][1]);
        }
#pragma unroll
        for (int i = 0; i < 4; i++) {
            float4 o; upk(a2[i][0], o.x, o.y); upk(a2[i][1], o.z, o.w);
            o.x *= scale; o.y *= scale; o.z *= scale; o.w *= scale;
            *(float4*)(g_qkt + (size_t)(n0 + r0 + i) * 512 + h * 128 + c0) = o;
        }
    }
}

// ---------------------------------------------------------------------------
// K2: attention core. One warp per node. Only rows s < L are read from HBM.
// mask_idx==0: reference's -1e9 on ALL positions annihilates score
// differences in fp32 -> softmax is exactly uniform 1/32. Skip key reads.
// ---------------------------------------------------------------------------
__global__ __launch_bounds__(256) void k2_kernel(
    const float* __restrict__ key, const float* __restrict__ value,
    const int* __restrict__ mask_idx)
{
    __shared__ float  sqk[8][4][128];
    __shared__ float4 sattn[8][32];

    const int w = threadIdx.x >> 5, l = threadIdx.x & 31;
    const int n = blockIdx.x * 8 + w;

    const int mi = mask_idx[n];
    const int L = (mi == 0) ? 32 : mi;

    if (mi == 0) {
        // uniform attention (fp32-exact reference behavior)
        const float ua = 1.0f / 32.0f;
        sattn[w][l] = make_float4(ua, ua, ua, ua);
    } else {
        {
            const float4* qsrc = (const float4*)(g_qkt + (size_t)n * 512);
#pragma unroll
            for (int h = 0; h < 4; h++)
                *(float4*)&sqk[w][h][4 * l] = qsrc[h * 32 + l];
        }
        __syncwarp();

        float sc[4] = {-INFINITY, -INFINITY, -INFINITY, -INFINITY};
        if (l < L) {
            const float4* krow = (const float4*)(key + ((size_t)l * NODES + n) * 128);
            float s0 = 0.f, s1 = 0.f, s2 = 0.f, s3 = 0.f;
#pragma unroll 4
            for (int c = 0; c < 32; c++) {
                float4 kv = krow[c];
                float4 q0 = *(const float4*)&sqk[w][0][4 * c];
                float4 q1 = *(const float4*)&sqk[w][1][4 * c];
                float4 q2 = *(const float4*)&sqk[w][2][4 * c];
                float4 q3 = *(const float4*)&sqk[w][3][4 * c];
                s0 = fmaf(kv.x, q0.x, fmaf(kv.y, q0.y, fmaf(kv.z, q0.z, fmaf(kv.w, q0.w, s0))));
                s1 = fmaf(kv.x, q1.x, fmaf(kv.y, q1.y, fmaf(kv.z, q1.z, fmaf(kv.w, q1.w, s1))));
                s2 = fmaf(kv.x, q2.x, fmaf(kv.y, q2.y, fmaf(kv.z, q2.z, fmaf(kv.w, q2.w, s2))));
                s3 = fmaf(kv.x, q3.x, fmaf(kv.y, q3.y, fmaf(kv.z, q3.z, fmaf(kv.w, q3.w, s3))));
            }
            sc[0] = s0; sc[1] = s1; sc[2] = s2; sc[3] = s3;
        }

        float at[4];
#pragma unroll
        for (int h = 0; h < 4; h++) {
            float m = sc[h];
#pragma unroll
            for (int off = 16; off; off >>= 1)
                m = fmaxf(m, __shfl_xor_sync(0xffffffffu, m, off));
            float e = __expf(sc[h] - m);   // -inf -> 0 exactly for masked lanes
            float ssum = e;
#pragma unroll
            for (int off = 16; off; off >>= 1)
                ssum += __shfl_xor_sync(0xffffffffu, ssum, off);
            at[h] = e / ssum;
        }
        sattn[w][l] = make_float4(at[0], at[1], at[2], at[3]);
    }
    __syncwarp();

    float u0[4] = {0,0,0,0}, u1[4] = {0,0,0,0}, u2[4] = {0,0,0,0}, u3[4] = {0,0,0,0};
    for (int s = 0; s < L; s++) {
        float4 a = sattn[w][s];
        float4 v = *(const float4*)(value + ((size_t)s * NODES + n) * 128 + 4 * l);
        float vv[4] = {v.x, v.y, v.z, v.w};
#pragma unroll
        for (int j = 0; j < 4; j++) {
            u0[j] = fmaf(a.x, vv[j], u0[j]);
            u1[j] = fmaf(a.y, vv[j], u1[j]);
            u2[j] = fmaf(a.z, vv[j], u2[j]);
            u3[j] = fmaf(a.w, vv[j], u3[j]);
        }
    }
    float* ub = g_u + (size_t)n * 512 + 4 * l;
    *(float4*)(ub +   0) = make_float4(u0[0], u0[1], u0[2], u0[3]);
    *(float4*)(ub + 128) = make_float4(u1[0], u1[1], u1[2], u1[3]);
    *(float4*)(ub + 256) = make_float4(u2[0], u2[1], u2[2], u2[3]);
    *(float4*)(ub + 384) = make_float4(u3[0], u3[1], u3[2], u3[3]);
}

// ---------------------------------------------------------------------------
// K3: wv = u@Wv(per-head) + bv;  out = wv@Wo + bo;  LN;  + query
// ---------------------------------------------------------------------------
__global__ __launch_bounds__(256) void k3_kernel(
    const float* __restrict__ Wv, const float* __restrict__ bv,
    const float* __restrict__ Wo, const float* __restrict__ bo,
    const float* __restrict__ gamma, const float* __restrict__ beta,
    const float* __restrict__ query, float* __restrict__ out)
{
    extern __shared__ float sm[];
    float* sUt  = sm;                    // 512*36 = 18432 (u^T, stride 36)
    float* buf0 = sm + 18432;            // 16384: Wv, then Wo
    float* swvt = sm + 18432 + 16384;    // 4608: wv^T (stride 36)

    const int t = threadIdx.x;
    const int n0 = blockIdx.x * 32;
    const int lane = t & 31, wg = t >> 5;
    const int c0 = 4 * lane, r0 = 4 * wg;

    // u^T fill (lane = row: conflict-free smem writes)
#pragma unroll
    for (int i = 0; i < 16; i++) {
        int cc = wg + 8 * i;  // float4 column 0..127
        float4 v = *(const float4*)(g_u + (size_t)(n0 + lane) * 512 + 4 * cc);
        sUt[(4 * cc + 0) * 36 + lane] = v.x; sUt[(4 * cc + 1) * 36 + lane] = v.y;
        sUt[(4 * cc + 2) * 36 + lane] = v.z; sUt[(4 * cc + 3) * 36 + lane] = v.w;
    }
    { const float4* s = (const float4*)Wv; float4* d = (float4*)buf0;
#pragma unroll
      for (int i = 0; i < 16; i++) d[t + 256 * i] = s[t + 256 * i]; }
    __syncthreads();

    // stage A: wv[r, c0..c0+3], head h = c0>>5
    {
        const int h = c0 >> 5;
        ull acc[4][2];
#pragma unroll
        for (int i = 0; i < 4; i++) { acc[i][0] = 0ull; acc[i][1] = 0ull; }
#pragma unroll 4
        for (int f = 0; f < 128; f++) {
            float4 a = *(const float4*)(sUt + (h * 128 + f) * 36 + r0);
            ulonglong2 b = *(const ulonglong2*)(buf0 + f * 128 + c0);
            ull A;
            A = pk2(a.x); acc[0][0] = ffma2(A, b.x, acc[0][0]); acc[0][1] = ffma2(A, b.y, acc[0][1]);
            A = pk2(a.y); acc[1][0] = ffma2(A, b.x, acc[1][0]); acc[1][1] = ffma2(A, b.y, acc[1][1]);
            A = pk2(a.z); acc[2][0] = ffma2(A, b.x, acc[2][0]); acc[2][1] = ffma2(A, b.y, acc[2][1]);
            A = pk2(a.w); acc[3][0] = ffma2(A, b.x, acc[3][0]); acc[3][1] = ffma2(A, b.y, acc[3][1]);
        }
        float4 b4 = *(const float4*)(bv + c0);
        float wv4[4][4];
#pragma unroll
        for (int i = 0; i < 4; i++) {
            upk(acc[i][0], wv4[i][0], wv4[i][1]); upk(acc[i][1], wv4[i][2], wv4[i][3]);
            wv4[i][0] += b4.x; wv4[i][1] += b4.y; wv4[i][2] += b4.z; wv4[i][3] += b4.w;
        }
        __syncthreads();
#pragma unroll
        for (int i = 0; i < 4; i++)
#pragma unroll
            for (int j = 0; j < 4; j++) swvt[(c0 + j) * 36 + r0 + i] = wv4[i][j];
    }
    { const float4* s = (const float4*)Wo; float4* d = (float4*)buf0;
#pragma unroll
      for (int i = 0; i < 16; i++) d[t + 256 * i] = s[t + 256 * i]; }
    __syncthreads();

    // stage B: out = wv @ Wo + bo, LN, residual
    ull acc[4][2];
#pragma unroll
    for (int i = 0; i < 4; i++) { acc[i][0] = 0ull; acc[i][1] = 0ull; }
#pragma unroll 4
    for (int k = 0; k < 128; k++) {
        float4 a = *(const float4*)(swvt + k * 36 + r0);
        ulonglong2 b = *(const ulonglong2*)(buf0 + k * 128 + c0);
        ull A;
        A = pk2(a.x); acc[0][0] = ffma2(A, b.x, acc[0][0]); acc[0][1] = ffma2(A, b.y, acc[0][1]);
        A = pk2(a.y); acc[1][0] = ffma2(A, b.x, acc[1][0]); acc[1][1] = ffma2(A, b.y, acc[1][1]);
        A = pk2(a.z); acc[2][0] = ffma2(A, b.x, acc[2][0]); acc[2][1] = ffma2(A, b.y, acc[2][1]);
        A = pk2(a.w); acc[3][0] = ffma2(A, b.x, acc[3][0]); acc[3][1] = ffma2(A, b.y, acc[3][1]);
    }

    float4 bo4 = *(const float4*)(bo + c0);
    float4 g4  = *(const float4*)(gamma + c0);
    float4 be4 = *(const float4*)(beta + c0);

#pragma unroll
    for (int i = 0; i < 4; i++) {
        float o[4];
        upk(acc[i][0], o[0], o[1]); upk(acc[i][1], o[2], o[3]);
        o[0] += bo4.x; o[1] += bo4.y; o[2] += bo4.z; o[3] += bo4.w;
        float s  = o[0] + o[1] + o[2] + o[3];
        float sq = o[0]*o[0] + o[1]*o[1] + o[2]*o[2] + o[3]*o[3];
#pragma unroll
        for (int off = 16; off; off >>= 1) {
            s  += __shfl_xor_sync(0xffffffffu, s, off);
            sq += __shfl_xor_sync(0xffffffffu, sq, off);
        }
        float mu = s * (1.f / 128.f);
        float var = sq * (1.f / 128.f) - mu * mu;
        float rstd = rsqrtf(var + 1e-5f);
        float4 q4 = *(const float4*)(query + (size_t)(n0 + r0 + i) * 128 + c0);
        float4 res;
        res.x = q4.x + (o[0] - mu) * rstd * g4.x + be4.x;
        res.y = q4.y + (o[1] - mu) * rstd * g4.y + be4.y;
        res.z = q4.z + (o[2] - mu) * rstd * g4.z + be4.z;
        res.w = q4.w + (o[3] - mu) * rstd * g4.w + be4.w;
        *(float4*)(out + (size_t)(n0 + r0 + i) * 128 + c0) = res;
    }
}

extern "C" void kernel_launch(void* const* d_in, const int* in_sizes, int n_in,
                              void* d_out, int out_size) {
    const float* query = (const float*)d_in[0];
    const float* key   = (const float*)d_in[1];
    const float* value = (const float*)d_in[2];
    const int*   midx  = (const int*)d_in[3];
    const float* Wq = (const float*)d_in[4];
    const float* bq = (const float*)d_in[5];
    const float* Wk = (const float*)d_in[6];
    // bk = d_in[7] cancels in softmax (and is zero) — unused
    const float* Wv = (const float*)d_in[8];
    const float* bv = (const float*)d_in[9];
    const float* Wo = (const float*)d_in[10];
    const float* bo = (const float*)d_in[11];
    const float* gamma = (const float*)d_in[12];
    const float* beta  = (const float*)d_in[13];
    float* out = (float*)d_out;

    const int smem1 = (16384 + 4608) * 4;
    const int smem3 = (18432 + 16384 + 4608) * 4;
    cudaFuncSetAttribute(k1_kernel, cudaFuncAttributeMaxDynamicSharedMemorySize, smem1);
    cudaFuncSetAttribute(k3_kernel, cudaFuncAttributeMaxDynamicSharedMemorySize, smem3);

    k1_kernel<<<NODES / 32, 256, smem1>>>(query, Wq, bq, Wk);
    k2_kernel<<<NODES / 8, 256>>>(key, value, midx);
    k3_kernel<<<NODES / 32, 256, smem3>>>(Wv, bv, Wo, bo, gamma, beta, query, out);
}

// round 9
// speedup vs baseline: 1.0115x; 1.0115x over previous
#include <cuda_runtime.h>
#include <math.h>

#define NODES 20000

typedef unsigned long long ull;

__device__ float g_qkt[(size_t)NODES * 512];
__device__ float g_u[(size_t)NODES * 512];

__device__ __forceinline__ ull pk2(float x) {
    unsigned xi = __float_as_uint(x);
    ull r;
    asm("mov.b64 %0, {%1, %1};" : "=l"(r) : "r"(xi), "r"(xi));
    return r;
}
__device__ __forceinline__ ull ffma2(ull a, ull b, ull c) {
    ull d;
    asm("fma.rn.f32x2 %0, %1, %2, %3;" : "=l"(d) : "l"(a), "l"(b), "l"(c));
    return d;
}
__device__ __forceinline__ void upk(ull v, float& lo, float& hi) {
    unsigned a, b;
    asm("mov.b64 {%0, %1}, %2;" : "=r"(a), "=r"(b) : "l"(v));
    lo = __uint_as_float(a); hi = __uint_as_float(b);
}

// 8-row x 4-col micro-kernel step over 4 k-values.
// bA: A tile base (row-major, stride 132), r0: first row, kbase: k offset in A cols
// bW: B tile base ([k][128]), klocal: k offset in B rows, c0: col
#define GEMM_STEP_8x4(bA, r0, kbase, bW, klocal, c0, acc)                              \
    {                                                                                   \
        ulonglong2 b0 = *(const ulonglong2*)((bW) + ((klocal) + 0) * 128 + (c0));       \
        ulonglong2 b1 = *(const ulonglong2*)((bW) + ((klocal) + 1) * 128 + (c0));       \
        ulonglong2 b2 = *(const ulonglong2*)((bW) + ((klocal) + 2) * 128 + (c0));       \
        ulonglong2 b3 = *(const ulonglong2*)((bW) + ((klocal) + 3) * 128 + (c0));       \
        _Pragma("unroll")                                                               \
        for (int i = 0; i < 8; i++) {                                                   \
            float4 a = *(const float4*)((bA) + ((r0) + i) * 132 + (kbase));             \
            ull A;                                                                      \
            A = pk2(a.x); acc[i][0] = ffma2(A, b0.x, acc[i][0]); acc[i][1] = ffma2(A, b0.y, acc[i][1]); \
            A = pk2(a.y); acc[i][0] = ffma2(A, b1.x, acc[i][0]); acc[i][1] = ffma2(A, b1.y, acc[i][1]); \
            A = pk2(a.z); acc[i][0] = ffma2(A, b2.x, acc[i][0]); acc[i][1] = ffma2(A, b2.y, acc[i][1]); \
            A = pk2(a.w); acc[i][0] = ffma2(A, b3.x, acc[i][0]); acc[i][1] = ffma2(A, b3.y, acc[i][1]); \
        }                                                                               \
    }

// ---------------------------------------------------------------------------
// K1: q = query@Wq + bq;  qkt[n,h,g] = scale * sum_d q[h,d] * Wk[g, h*32+d]
// 64 nodes/CTA, 8x4 tiles, weights staged in two 64-k chunks.
// ---------------------------------------------------------------------------
__global__ __launch_bounds__(256, 2) void k1_kernel(
    const float* __restrict__ query, const float* __restrict__ Wq,
    const float* __restrict__ bq, const float* __restrict__ Wk)
{
    extern __shared__ float sm[];
    float* bufW = sm;                   // 64*128 = 8192 floats (weight chunk)
    float* bufA = sm + 8192;            // 64*132 = 8448 (query tile, row-major)
    float* bufQ = sm + 8192 + 8448;     // 8448 (Q tile, row-major)

    const int t = threadIdx.x;
    const int n0 = blockIdx.x * 64;
    const int lane = t & 31, wg = t >> 5;
    const int c0 = 4 * lane, r0 = 8 * wg;

    // load A tile (query rows, guarded)
    {
        const int r = t & 63, part = t >> 6;  // part 0..3, 32 floats each
        float* dst = bufA + r * 132 + part * 32;
        if (n0 + r < NODES) {
            const float* src = query + (size_t)(n0 + r) * 128 + part * 32;
#pragma unroll
            for (int j = 0; j < 8; j++) *(float4*)(dst + 4 * j) = *(const float4*)(src + 4 * j);
        } else {
#pragma unroll
            for (int j = 0; j < 8; j++) *(float4*)(dst + 4 * j) = make_float4(0.f, 0.f, 0.f, 0.f);
        }
    }

    // stage A: Q = A @ Wq + bq
    ull acc[8][2];
#pragma unroll
    for (int i = 0; i < 8; i++) { acc[i][0] = 0ull; acc[i][1] = 0ull; }

    for (int ch = 0; ch < 2; ch++) {
        __syncthreads();
        { const float4* s = (const float4*)(Wq + (size_t)64 * ch * 128);
          float4* d = (float4*)bufW;
#pragma unroll
          for (int i = 0; i < 8; i++) d[t + 256 * i] = s[t + 256 * i]; }
        __syncthreads();
#pragma unroll 2
        for (int kk = 0; kk < 64; kk += 4) {
            GEMM_STEP_8x4(bufA, r0, 64 * ch + kk, bufW, kk, c0, acc);
        }
    }

    // bias, write Q row-major (conflict-free float4 stores)
    {
        float4 b4 = *(const float4*)(bq + c0);
#pragma unroll
        for (int i = 0; i < 8; i++) {
            float lo0, hi0, lo1, hi1;
            upk(acc[i][0], lo0, hi0); upk(acc[i][1], lo1, hi1);
            *(float4*)(bufQ + (r0 + i) * 132 + c0) =
                make_float4(lo0 + b4.x, hi0 + b4.y, lo1 + b4.z, hi1 + b4.w);
        }
    }

    // stage B: per-head qkt, Wk^T staged in two 64-k2 chunks
    const float scale = 0.17677669529663688f;  // 1/sqrt(32)
    for (int ch = 0; ch < 2; ch++) {
        __syncthreads();
        {   // bufW[k2local][g] = Wk[g][64*ch + k2local]
            const int g = t & 127, pr = t >> 7;  // pr 0..1
#pragma unroll
            for (int jj = 0; jj < 8; jj++) {
                float4 v = *(const float4*)(Wk + (size_t)g * 128 + 64 * ch + pr * 32 + 4 * jj);
                bufW[(pr * 32 + 4 * jj + 0) * 128 + g] = v.x;
                bufW[(pr * 32 + 4 * jj + 1) * 128 + g] = v.y;
                bufW[(pr * 32 + 4 * jj + 2) * 128 + g] = v.z;
                bufW[(pr * 32 + 4 * jj + 3) * 128 + g] = v.w;
            }
        }
        __syncthreads();
#pragma unroll
        for (int hh = 0; hh < 2; hh++) {
            const int h = 2 * ch + hh;
            ull a2[8][2];
#pragma unroll
            for (int i = 0; i < 8; i++) { a2[i][0] = 0ull; a2[i][1] = 0ull; }
#pragma unroll 2
            for (int dd = 0; dd < 32; dd += 4) {
                GEMM_STEP_8x4(bufQ, r0, h * 32 + dd, bufW, hh * 32 + dd, c0, a2);
            }
#pragma unroll
            for (int i = 0; i < 8; i++) {
                if (n0 + r0 + i < NODES) {
                    float4 o;
                    upk(a2[i][0], o.x, o.y); upk(a2[i][1], o.z, o.w);
                    o.x *= scale; o.y *= scale; o.z *= scale; o.w *= scale;
                    *(float4*)(g_qkt + (size_t)(n0 + r0 + i) * 512 + h * 128 + c0) = o;
                }
            }
        }
    }
}

// ---------------------------------------------------------------------------
// K2: attention core. One warp per node. Only rows s < L are read from HBM.
// mask_idx==0: reference's -1e9 on ALL positions annihilates score
// differences in fp32 -> softmax is exactly uniform 1/32. Skip key reads.
// ---------------------------------------------------------------------------
__global__ __launch_bounds__(256) void k2_kernel(
    const float* __restrict__ key, const float* __restrict__ value,
    const int* __restrict__ mask_idx)
{
    __shared__ float  sqk[8][4][128];
    __shared__ float4 sattn[8][32];

    const int w = threadIdx.x >> 5, l = threadIdx.x & 31;
    const int n = blockIdx.x * 8 + w;

    const int mi = mask_idx[n];
    const int L = (mi == 0) ? 32 : mi;

    if (mi == 0) {
        const float ua = 1.0f / 32.0f;
        sattn[w][l] = make_float4(ua, ua, ua, ua);
    } else {
        {
            const float4* qsrc = (const float4*)(g_qkt + (size_t)n * 512);
#pragma unroll
            for (int h = 0; h < 4; h++)
                *(float4*)&sqk[w][h][4 * l] = qsrc[h * 32 + l];
        }
        __syncwarp();

        float sc[4] = {-INFINITY, -INFINITY, -INFINITY, -INFINITY};
        if (l < L) {
            const float4* krow = (const float4*)(key + ((size_t)l * NODES + n) * 128);
            float s0 = 0.f, s1 = 0.f, s2 = 0.f, s3 = 0.f;
#pragma unroll 4
            for (int c = 0; c < 32; c++) {
                float4 kv = krow[c];
                float4 q0 = *(const float4*)&sqk[w][0][4 * c];
                float4 q1 = *(const float4*)&sqk[w][1][4 * c];
                float4 q2 = *(const float4*)&sqk[w][2][4 * c];
                float4 q3 = *(const float4*)&sqk[w][3][4 * c];
                s0 = fmaf(kv.x, q0.x, fmaf(kv.y, q0.y, fmaf(kv.z, q0.z, fmaf(kv.w, q0.w, s0))));
                s1 = fmaf(kv.x, q1.x, fmaf(kv.y, q1.y, fmaf(kv.z, q1.z, fmaf(kv.w, q1.w, s1))));
                s2 = fmaf(kv.x, q2.x, fmaf(kv.y, q2.y, fmaf(kv.z, q2.z, fmaf(kv.w, q2.w, s2))));
                s3 = fmaf(kv.x, q3.x, fmaf(kv.y, q3.y, fmaf(kv.z, q3.z, fmaf(kv.w, q3.w, s3))));
            }
            sc[0] = s0; sc[1] = s1; sc[2] = s2; sc[3] = s3;
        }

        float at[4];
#pragma unroll
        for (int h = 0; h < 4; h++) {
            float m = sc[h];
#pragma unroll
            for (int off = 16; off; off >>= 1)
                m = fmaxf(m, __shfl_xor_sync(0xffffffffu, m, off));
            float e = __expf(sc[h] - m);
            float ssum = e;
#pragma unroll
            for (int off = 16; off; off >>= 1)
                ssum += __shfl_xor_sync(0xffffffffu, ssum, off);
            at[h] = e / ssum;
        }
        sattn[w][l] = make_float4(at[0], at[1], at[2], at[3]);
    }
    __syncwarp();

    float u0[4] = {0,0,0,0}, u1[4] = {0,0,0,0}, u2[4] = {0,0,0,0}, u3[4] = {0,0,0,0};
    for (int s = 0; s < L; s++) {
        float4 a = sattn[w][s];
        float4 v = *(const float4*)(value + ((size_t)s * NODES + n) * 128 + 4 * l);
        float vv[4] = {v.x, v.y, v.z, v.w};
#pragma unroll
        for (int j = 0; j < 4; j++) {
            u0[j] = fmaf(a.x, vv[j], u0[j]);
            u1[j] = fmaf(a.y, vv[j], u1[j]);
            u2[j] = fmaf(a.z, vv[j], u2[j]);
            u3[j] = fmaf(a.w, vv[j], u3[j]);
        }
    }
    float* ub = g_u + (size_t)n * 512 + 4 * l;
    *(float4*)(ub +   0) = make_float4(u0[0], u0[1], u0[2], u0[3]);
    *(float4*)(ub + 128) = make_float4(u1[0], u1[1], u1[2], u1[3]);
    *(float4*)(ub + 256) = make_float4(u2[0], u2[1], u2[2], u2[3]);
    *(float4*)(ub + 384) = make_float4(u3[0], u3[1], u3[2], u3[3]);
}

// ---------------------------------------------------------------------------
// K3: wv = u@Wv(per-head) + bv;  out = wv@Wo + bo;  LN;  + query
// 64 nodes/CTA. Stage A per-head (u slice 64x128), stage B 8x4 tiles with
// Wo chunked. smem 84KB -> 2 CTAs/SM.
// ---------------------------------------------------------------------------
__global__ __launch_bounds__(256, 2) void k3_kernel(
    const float* __restrict__ Wv, const float* __restrict__ bv,
    const float* __restrict__ Wo, const float* __restrict__ bo,
    const float* __restrict__ gamma, const float* __restrict__ beta,
    const float* __restrict__ query, float* __restrict__ out)
{
    extern __shared__ float sm[];
    float* bufU  = sm;                     // 64*132 = 8448 floats (u head-slice)
    float* bufWs = sm + 8448;              // 128*36 = 4608 (Wv head-slice)
    float* bufWV = sm + 8448 + 4608;       // 64*132 = 8448 (wv, row-major)
    float* bufWo = sm;                     // stage B: Wo chunk [64][128] = 8192 (aliases bufU+bufWs)

    const int t = threadIdx.x;
    const int n0 = blockIdx.x * 64;
    const int lane = t & 31, wg = t >> 5;
    const int c0 = 4 * lane, r0 = 8 * wg;

    // ---- stage A: per-head wv ----
    for (int h = 0; h < 4; h++) {
        __syncthreads();
        {   // u head slice
            const int r = t & 63, part = t >> 6;
            float* dst = bufU + r * 132 + part * 32;
            if (n0 + r < NODES) {
                const float* src = g_u + (size_t)(n0 + r) * 512 + h * 128 + part * 32;
#pragma unroll
                for (int j = 0; j < 8; j++) *(float4*)(dst + 4 * j) = *(const float4*)(src + 4 * j);
            } else {
#pragma unroll
                for (int j = 0; j < 8; j++) *(float4*)(dst + 4 * j) = make_float4(0.f, 0.f, 0.f, 0.f);
            }
        }
        {   // Wv head slice: bufWs[f][c] = Wv[f][h*32+c], c 0..31, stride 36
            const int f = t & 127, qq = t >> 7;  // qq 0..1 -> 16 cols each
#pragma unroll
            for (int jj = 0; jj < 4; jj++) {
                float4 v = *(const float4*)(Wv + (size_t)f * 128 + h * 32 + qq * 16 + 4 * jj);
                *(float4*)(bufWs + f * 36 + qq * 16 + 4 * jj) = v;
            }
        }
        __syncthreads();

        // 2 rows x 4 cols per thread: 32 col-slots? head has 32 cols -> 8 col groups
        const int cg = lane & 7, rg = wg * 4 + (lane >> 3);  // rg 0..31
        const int c0h = 4 * cg, rr0 = 2 * rg;
        ull acc[2][2];
        acc[0][0] = acc[0][1] = acc[1][0] = acc[1][1] = 0ull;
#pragma unroll 4
        for (int f = 0; f < 128; f += 4) {
            ulonglong2 b0 = *(const ulonglong2*)(bufWs + (f + 0) * 36 + c0h);
            ulonglong2 b1 = *(const ulonglong2*)(bufWs + (f + 1) * 36 + c0h);
            ulonglong2 b2 = *(const ulonglong2*)(bufWs + (f + 2) * 36 + c0h);
            ulonglong2 b3 = *(const ulonglong2*)(bufWs + (f + 3) * 36 + c0h);
#pragma unroll
            for (int i = 0; i < 2; i++) {
                float4 a = *(const float4*)(bufU + (rr0 + i) * 132 + f);
                ull A;
                A = pk2(a.x); acc[i][0] = ffma2(A, b0.x, acc[i][0]); acc[i][1] = ffma2(A, b0.y, acc[i][1]);
                A = pk2(a.y); acc[i][0] = ffma2(A, b1.x, acc[i][0]); acc[i][1] = ffma2(A, b1.y, acc[i][1]);
                A = pk2(a.z); acc[i][0] = ffma2(A, b2.x, acc[i][0]); acc[i][1] = ffma2(A, b2.y, acc[i][1]);
                A = pk2(a.w); acc[i][0] = ffma2(A, b3.x, acc[i][0]); acc[i][1] = ffma2(A, b3.y, acc[i][1]);
            }
        }
        float4 bvv = *(const float4*)(bv + h * 32 + c0h);
#pragma unroll
        for (int i = 0; i < 2; i++) {
            float lo0, hi0, lo1, hi1;
            upk(acc[i][0], lo0, hi0); upk(acc[i][1], lo1, hi1);
            *(float4*)(bufWV + (rr0 + i) * 132 + h * 32 + c0h) =
                make_float4(lo0 + bvv.x, hi0 + bvv.y, lo1 + bvv.z, hi1 + bvv.w);
        }
    }

    // ---- stage B: out = wv @ Wo + bo, LN, residual ----
    ull acc[8][2];
#pragma unroll
    for (int i = 0; i < 8; i++) { acc[i][0] = 0ull; acc[i][1] = 0ull; }
    for (int ch = 0; ch < 2; ch++) {
        __syncthreads();
        { const float4* s = (const float4*)(Wo + (size_t)64 * ch * 128);
          float4* d = (float4*)bufWo;
#pragma unroll
          for (int i = 0; i < 8; i++) d[t + 256 * i] = s[t + 256 * i]; }
        __syncthreads();
#pragma unroll 2
        for (int kk = 0; kk < 64; kk += 4) {
            GEMM_STEP_8x4(bufWV, r0, 64 * ch + kk, bufWo, kk, c0, acc);
        }
    }

    float4 bo4 = *(const float4*)(bo + c0);
    float4 g4  = *(const float4*)(gamma + c0);
    float4 be4 = *(const float4*)(beta + c0);

#pragma unroll
    for (int i = 0; i < 8; i++) {
        float o[4];
        upk(acc[i][0], o[0], o[1]); upk(acc[i][1], o[2], o[3]);
        o[0] += bo4.x; o[1] += bo4.y; o[2] += bo4.z; o[3] += bo4.w;
        float s  = o[0] + o[1] + o[2] + o[3];
        float sq = o[0]*o[0] + o[1]*o[1] + o[2]*o[2] + o[3]*o[3];
#pragma unroll
        for (int off = 16; off; off >>= 1) {
            s  += __shfl_xor_sync(0xffffffffu, s, off);
            sq += __shfl_xor_sync(0xffffffffu, sq, off);
        }
        const int row = n0 + r0 + i;
        if (row < NODES) {
            float mu = s * (1.f / 128.f);
            float var = sq * (1.f / 128.f) - mu * mu;
            float rstd = rsqrtf(var + 1e-5f);
            float4 q4 = *(const float4*)(query + (size_t)row * 128 + c0);
            float4 res;
            res.x = q4.x + (o[0] - mu) * rstd * g4.x + be4.x;
            res.y = q4.y + (o[1] - mu) * rstd * g4.y + be4.y;
            res.z = q4.z + (o[2] - mu) * rstd * g4.z + be4.z;
            res.w = q4.w + (o[3] - mu) * rstd * g4.w + be4.w;
            *(float4*)(out + (size_t)row * 128 + c0) = res;
        }
    }
}

extern "C" void kernel_launch(void* const* d_in, const int* in_sizes, int n_in,
                              void* d_out, int out_size) {
    const float* query = (const float*)d_in[0];
    const float* key   = (const float*)d_in[1];
    const float* value = (const float*)d_in[2];
    const int*   midx  = (const int*)d_in[3];
    const float* Wq = (const float*)d_in[4];
    const float* bq = (const float*)d_in[5];
    const float* Wk = (const float*)d_in[6];
    // bk = d_in[7] cancels in softmax (and is zero) — unused
    const float* Wv = (const float*)d_in[8];
    const float* bv = (const float*)d_in[9];
    const float* Wo = (const float*)d_in[10];
    const float* bo = (const float*)d_in[11];
    const float* gamma = (const float*)d_in[12];
    const float* beta  = (const float*)d_in[13];
    float* out = (float*)d_out;

    const int smem1 = (8192 + 8448 + 8448) * 4;            // 100,352 B
    const int smem3 = (8448 + 4608 + 8448) * 4;            // 86,016 B
    cudaFuncSetAttribute(k1_kernel, cudaFuncAttributeMaxDynamicSharedMemorySize, smem1);
    cudaFuncSetAttribute(k3_kernel, cudaFuncAttributeMaxDynamicSharedMemorySize, smem3);

    const int grid14 = (NODES + 63) / 64;  // 313
    k1_kernel<<<grid14, 256, smem1>>>(query, Wq, bq, Wk);
    k2_kernel<<<NODES / 8, 256>>>(key, value, midx);
    k3_kernel<<<grid14, 256, smem3>>>(Wv, bv, Wo, bo, gamma, beta, query, out);
}

// round 10
// speedup vs baseline: 1.0562x; 1.0442x over previous
#include <cuda_runtime.h>
#include <math.h>

#define NODES 20000

typedef unsigned long long ull;

__device__ float g_qkt[(size_t)NODES * 512];
__device__ float g_u[(size_t)NODES * 512];

__device__ __forceinline__ ull pk2(float x) {
    unsigned xi = __float_as_uint(x);
    ull r;
    asm("mov.b64 %0, {%1, %1};" : "=l"(r) : "r"(xi), "r"(xi));
    return r;
}
__device__ __forceinline__ ull ffma2(ull a, ull b, ull c) {
    ull d;
    asm("fma.rn.f32x2 %0, %1, %2, %3;" : "=l"(d) : "l"(a), "l"(b), "l"(c));
    return d;
}
__device__ __forceinline__ void upk(ull v, float& lo, float& hi) {
    unsigned a, b;
    asm("mov.b64 {%0, %1}, %2;" : "=r"(a), "=r"(b) : "l"(v));
    lo = __uint_as_float(a); hi = __uint_as_float(b);
}

// 8-row x 4-col micro-kernel step over 4 k-values.
#define GEMM_STEP_8x4(bA, r0, kbase, bW, klocal, c0, acc)                              \
    {                                                                                   \
        ulonglong2 b0 = *(const ulonglong2*)((bW) + ((klocal) + 0) * 128 + (c0));       \
        ulonglong2 b1 = *(const ulonglong2*)((bW) + ((klocal) + 1) * 128 + (c0));       \
        ulonglong2 b2 = *(const ulonglong2*)((bW) + ((klocal) + 2) * 128 + (c0));       \
        ulonglong2 b3 = *(const ulonglong2*)((bW) + ((klocal) + 3) * 128 + (c0));       \
        _Pragma("unroll")                                                               \
        for (int i = 0; i < 8; i++) {                                                   \
            float4 a = *(const float4*)((bA) + ((r0) + i) * 132 + (kbase));             \
            ull A;                                                                      \
            A = pk2(a.x); acc[i][0] = ffma2(A, b0.x, acc[i][0]); acc[i][1] = ffma2(A, b0.y, acc[i][1]); \
            A = pk2(a.y); acc[i][0] = ffma2(A, b1.x, acc[i][0]); acc[i][1] = ffma2(A, b1.y, acc[i][1]); \
            A = pk2(a.z); acc[i][0] = ffma2(A, b2.x, acc[i][0]); acc[i][1] = ffma2(A, b2.y, acc[i][1]); \
            A = pk2(a.w); acc[i][0] = ffma2(A, b3.x, acc[i][0]); acc[i][1] = ffma2(A, b3.y, acc[i][1]); \
        }                                                                               \
    }

// ---------------------------------------------------------------------------
// K1: q = query@Wq + bq;  qkt[n,h,g] = scale * sum_d q[h,d] * Wk[g, h*32+d]
// 64 nodes/CTA, 8x4 tiles. 32-k weight chunks (16KB). Q aliases the consumed
// A tile. smem = 50.2KB, 3 CTAs/SM -> single wave over 313 CTAs.
// ---------------------------------------------------------------------------
__global__ __launch_bounds__(256, 3) void k1_kernel(
    const float* __restrict__ query, const float* __restrict__ Wq,
    const float* __restrict__ bq, const float* __restrict__ Wk)
{
    extern __shared__ float sm[];
    float* bufW = sm;          // 32*128 = 4096 floats (weight chunk)
    float* bufA = sm + 4096;   // 64*132 = 8448 (query tile, later Q tile)

    const int t = threadIdx.x;
    const int n0 = blockIdx.x * 64;
    const int lane = t & 31, wg = t >> 5;
    const int c0 = 4 * lane, r0 = 8 * wg;

    // load A tile (query rows, guarded)
    {
        const int r = t & 63, part = t >> 6;  // part 0..3, 32 floats each
        float* dst = bufA + r * 132 + part * 32;
        if (n0 + r < NODES) {
            const float* src = query + (size_t)(n0 + r) * 128 + part * 32;
#pragma unroll
            for (int j = 0; j < 8; j++) *(float4*)(dst + 4 * j) = *(const float4*)(src + 4 * j);
        } else {
#pragma unroll
            for (int j = 0; j < 8; j++) *(float4*)(dst + 4 * j) = make_float4(0.f, 0.f, 0.f, 0.f);
        }
    }

    // stage A: Q = A @ Wq + bq (4 chunks of 32 k)
    ull acc[8][2];
#pragma unroll
    for (int i = 0; i < 8; i++) { acc[i][0] = 0ull; acc[i][1] = 0ull; }

    for (int ch = 0; ch < 4; ch++) {
        __syncthreads();
        { const float4* s = (const float4*)(Wq + (size_t)32 * ch * 128);
          float4* d = (float4*)bufW;
#pragma unroll
          for (int i = 0; i < 4; i++) d[t + 256 * i] = s[t + 256 * i]; }
        __syncthreads();
#pragma unroll
        for (int kk = 0; kk < 32; kk += 4) {
            GEMM_STEP_8x4(bufA, r0, 32 * ch + kk, bufW, kk, c0, acc);
        }
    }

    // all stage-A reads of bufA done -> overwrite with Q (each warp its own rows)
    __syncthreads();
    {
        float4 b4 = *(const float4*)(bq + c0);
#pragma unroll
        for (int i = 0; i < 8; i++) {
            float lo0, hi0, lo1, hi1;
            upk(acc[i][0], lo0, hi0); upk(acc[i][1], lo1, hi1);
            *(float4*)(bufA + (r0 + i) * 132 + c0) =
                make_float4(lo0 + b4.x, hi0 + b4.y, lo1 + b4.z, hi1 + b4.w);
        }
    }

    // stage B: per-head qkt; Wk^T head slice [32 d][128 g] staged per head.
    const float scale = 0.17677669529663688f;  // 1/sqrt(32)
    for (int h = 0; h < 4; h++) {
        __syncthreads();
        {   // bufW[d][g] = Wk[g][h*32+d]
            const int g = t & 127, pr = t >> 7;  // pr 0..1 -> 16 d each
#pragma unroll
            for (int jj = 0; jj < 4; jj++) {
                float4 v = *(const float4*)(Wk + (size_t)g * 128 + h * 32 + pr * 16 + 4 * jj);
                bufW[(pr * 16 + 4 * jj + 0) * 128 + g] = v.x;
                bufW[(pr * 16 + 4 * jj + 1) * 128 + g] = v.y;
                bufW[(pr * 16 + 4 * jj + 2) * 128 + g] = v.z;
                bufW[(pr * 16 + 4 * jj + 3) * 128 + g] = v.w;
            }
        }
        __syncthreads();

        ull a2[8][2];
#pragma unroll
        for (int i = 0; i < 8; i++) { a2[i][0] = 0ull; a2[i][1] = 0ull; }
#pragma unroll
        for (int dd = 0; dd < 32; dd += 4) {
            GEMM_STEP_8x4(bufA, r0, h * 32 + dd, bufW, dd, c0, a2);
        }
#pragma unroll
        for (int i = 0; i < 8; i++) {
            if (n0 + r0 + i < NODES) {
                float4 o;
                upk(a2[i][0], o.x, o.y); upk(a2[i][1], o.z, o.w);
                o.x *= scale; o.y *= scale; o.z *= scale; o.w *= scale;
                *(float4*)(g_qkt + (size_t)(n0 + r0 + i) * 512 + h * 128 + c0) = o;
            }
        }
    }
}

// ---------------------------------------------------------------------------
// K2: attention core. One warp per node. Only rows s < L are read from HBM.
// mask_idx==0: reference's -1e9 on ALL positions annihilates score
// differences in fp32 -> softmax is exactly uniform 1/32. Skip key reads.
// ---------------------------------------------------------------------------
__global__ __launch_bounds__(256) void k2_kernel(
    const float* __restrict__ key, const float* __restrict__ value,
    const int* __restrict__ mask_idx)
{
    __shared__ float  sqk[8][4][128];
    __shared__ float4 sattn[8][32];

    const int w = threadIdx.x >> 5, l = threadIdx.x & 31;
    const int n = blockIdx.x * 8 + w;

    const int mi = mask_idx[n];
    const int L = (mi == 0) ? 32 : mi;

    if (mi == 0) {
        const float ua = 1.0f / 32.0f;
        sattn[w][l] = make_float4(ua, ua, ua, ua);
    } else {
        {
            const float4* qsrc = (const float4*)(g_qkt + (size_t)n * 512);
#pragma unroll
            for (int h = 0; h < 4; h++)
                *(float4*)&sqk[w][h][4 * l] = qsrc[h * 32 + l];
        }
        __syncwarp();

        float sc[4] = {-INFINITY, -INFINITY, -INFINITY, -INFINITY};
        if (l < L) {
            const float4* krow = (const float4*)(key + ((size_t)l * NODES + n) * 128);
            float s0 = 0.f, s1 = 0.f, s2 = 0.f, s3 = 0.f;
#pragma unroll 4
            for (int c = 0; c < 32; c++) {
                float4 kv = krow[c];
                float4 q0 = *(const float4*)&sqk[w][0][4 * c];
                float4 q1 = *(const float4*)&sqk[w][1][4 * c];
                float4 q2 = *(const float4*)&sqk[w][2][4 * c];
                float4 q3 = *(const float4*)&sqk[w][3][4 * c];
                s0 = fmaf(kv.x, q0.x, fmaf(kv.y, q0.y, fmaf(kv.z, q0.z, fmaf(kv.w, q0.w, s0))));
                s1 = fmaf(kv.x, q1.x, fmaf(kv.y, q1.y, fmaf(kv.z, q1.z, fmaf(kv.w, q1.w, s1))));
                s2 = fmaf(kv.x, q2.x, fmaf(kv.y, q2.y, fmaf(kv.z, q2.z, fmaf(kv.w, q2.w, s2))));
                s3 = fmaf(kv.x, q3.x, fmaf(kv.y, q3.y, fmaf(kv.z, q3.z, fmaf(kv.w, q3.w, s3))));
            }
            sc[0] = s0; sc[1] = s1; sc[2] = s2; sc[3] = s3;
        }

        float at[4];
#pragma unroll
        for (int h = 0; h < 4; h++) {
            float m = sc[h];
#pragma unroll
            for (int off = 16; off; off >>= 1)
                m = fmaxf(m, __shfl_xor_sync(0xffffffffu, m, off));
            float e = __expf(sc[h] - m);
            float ssum = e;
#pragma unroll
            for (int off = 16; off; off >>= 1)
                ssum += __shfl_xor_sync(0xffffffffu, ssum, off);
            at[h] = e / ssum;
        }
        sattn[w][l] = make_float4(at[0], at[1], at[2], at[3]);
    }
    __syncwarp();

    float u0[4] = {0,0,0,0}, u1[4] = {0,0,0,0}, u2[4] = {0,0,0,0}, u3[4] = {0,0,0,0};
    const float* vbase = value + (size_t)n * 128 + 4 * l;
    int s = 0;
    for (; s + 2 <= L; s += 2) {
        float4 a  = sattn[w][s];
        float4 a2 = sattn[w][s + 1];
        float4 v  = *(const float4*)(vbase + (size_t)s * (NODES * 128));
        float4 v2 = *(const float4*)(vbase + (size_t)(s + 1) * (NODES * 128));
        float vv[4]  = {v.x, v.y, v.z, v.w};
        float vv2[4] = {v2.x, v2.y, v2.z, v2.w};
#pragma unroll
        for (int j = 0; j < 4; j++) {
            u0[j] = fmaf(a.x, vv[j], u0[j]);  u0[j] = fmaf(a2.x, vv2[j], u0[j]);
            u1[j] = fmaf(a.y, vv[j], u1[j]);  u1[j] = fmaf(a2.y, vv2[j], u1[j]);
            u2[j] = fmaf(a.z, vv[j], u2[j]);  u2[j] = fmaf(a2.z, vv2[j], u2[j]);
            u3[j] = fmaf(a.w, vv[j], u3[j]);  u3[j] = fmaf(a2.w, vv2[j], u3[j]);
        }
    }
    if (s < L) {
        float4 a = sattn[w][s];
        float4 v = *(const float4*)(vbase + (size_t)s * (NODES * 128));
        float vv[4] = {v.x, v.y, v.z, v.w};
#pragma unroll
        for (int j = 0; j < 4; j++) {
            u0[j] = fmaf(a.x, vv[j], u0[j]);
            u1[j] = fmaf(a.y, vv[j], u1[j]);
            u2[j] = fmaf(a.z, vv[j], u2[j]);
            u3[j] = fmaf(a.w, vv[j], u3[j]);
        }
    }
    float* ub = g_u + (size_t)n * 512 + 4 * l;
    *(float4*)(ub +   0) = make_float4(u0[0], u0[1], u0[2], u0[3]);
    *(float4*)(ub + 128) = make_float4(u1[0], u1[1], u1[2], u1[3]);
    *(float4*)(ub + 256) = make_float4(u2[0], u2[1], u2[2], u2[3]);
    *(float4*)(ub + 384) = make_float4(u3[0], u3[1], u3[2], u3[3]);
}

// ---------------------------------------------------------------------------
// K3: wv = u@Wv(per-head) + bv;  out = wv@Wo + bo;  LN;  + query
// 64 nodes/CTA. Stage A holds wv in registers; bufWV aliases the dead
// bufU region; Wo chunks alias bufWs. smem peak 52.2KB -> 3 CTAs/SM.
// ---------------------------------------------------------------------------
__global__ __launch_bounds__(256, 3) void k3_kernel(
    const float* __restrict__ Wv, const float* __restrict__ bv,
    const float* __restrict__ Wo, const float* __restrict__ bo,
    const float* __restrict__ gamma, const float* __restrict__ beta,
    const float* __restrict__ query, float* __restrict__ out)
{
    extern __shared__ float sm[];
    float* bufU  = sm;                     // 64*132 = 8448 (u head-slice)
    float* bufWs = sm + 8448;              // 128*36 = 4608 (Wv head-slice)
    float* bufWV = sm;                     // stage B: wv tile (aliases bufU)
    float* bufWo = sm + 8448;              // stage B: Wo chunk [32][128] = 4096 (aliases bufWs)

    const int t = threadIdx.x;
    const int n0 = blockIdx.x * 64;
    const int lane = t & 31, wg = t >> 5;
    const int c0 = 4 * lane, r0 = 8 * wg;

    // stage A mapping: 2 rows x 4 cols per thread, per head
    const int cg = lane & 7, rg = wg * 4 + (lane >> 3);  // rg 0..31
    const int c0h = 4 * cg, rr0 = 2 * rg;

    float wvreg[4][2][4];  // [head][row][col]

    // ---- stage A: per-head wv (held in registers) ----
    for (int h = 0; h < 4; h++) {
        __syncthreads();
        {   // u head slice
            const int r = t & 63, part = t >> 6;
            float* dst = bufU + r * 132 + part * 32;
            if (n0 + r < NODES) {
                const float* src = g_u + (size_t)(n0 + r) * 512 + h * 128 + part * 32;
#pragma unroll
                for (int j = 0; j < 8; j++) *(float4*)(dst + 4 * j) = *(const float4*)(src + 4 * j);
            } else {
#pragma unroll
                for (int j = 0; j < 8; j++) *(float4*)(dst + 4 * j) = make_float4(0.f, 0.f, 0.f, 0.f);
            }
        }
        {   // Wv head slice: bufWs[f][c] = Wv[f][h*32+c], stride 36
            const int f = t & 127, qq = t >> 7;
#pragma unroll
            for (int jj = 0; jj < 4; jj++) {
                float4 v = *(const float4*)(Wv + (size_t)f * 128 + h * 32 + qq * 16 + 4 * jj);
                *(float4*)(bufWs + f * 36 + qq * 16 + 4 * jj) = v;
            }
        }
        __syncthreads();

        ull acc2[2][2];
        acc2[0][0] = acc2[0][1] = acc2[1][0] = acc2[1][1] = 0ull;
#pragma unroll 4
        for (int f = 0; f < 128; f += 4) {
            ulonglong2 b0 = *(const ulonglong2*)(bufWs + (f + 0) * 36 + c0h);
            ulonglong2 b1 = *(const ulonglong2*)(bufWs + (f + 1) * 36 + c0h);
            ulonglong2 b2 = *(const ulonglong2*)(bufWs + (f + 2) * 36 + c0h);
            ulonglong2 b3 = *(const ulonglong2*)(bufWs + (f + 3) * 36 + c0h);
#pragma unroll
            for (int i = 0; i < 2; i++) {
                float4 a = *(const float4*)(bufU + (rr0 + i) * 132 + f);
                ull A;
                A = pk2(a.x); acc2[i][0] = ffma2(A, b0.x, acc2[i][0]); acc2[i][1] = ffma2(A, b0.y, acc2[i][1]);
                A = pk2(a.y); acc2[i][0] = ffma2(A, b1.x, acc2[i][0]); acc2[i][1] = ffma2(A, b1.y, acc2[i][1]);
                A = pk2(a.z); acc2[i][0] = ffma2(A, b2.x, acc2[i][0]); acc2[i][1] = ffma2(A, b2.y, acc2[i][1]);
                A = pk2(a.w); acc2[i][0] = ffma2(A, b3.x, acc2[i][0]); acc2[i][1] = ffma2(A, b3.y, acc2[i][1]);
            }
        }
        float4 bvv = *(const float4*)(bv + h * 32 + c0h);
#pragma unroll
        for (int i = 0; i < 2; i++) {
            upk(acc2[i][0], wvreg[h][i][0], wvreg[h][i][1]);
            upk(acc2[i][1], wvreg[h][i][2], wvreg[h][i][3]);
            wvreg[h][i][0] += bvv.x; wvreg[h][i][1] += bvv.y;
            wvreg[h][i][2] += bvv.z; wvreg[h][i][3] += bvv.w;
        }
    }

    // all bufU/bufWs reads done -> write wv tile over the aliased region
    __syncthreads();
#pragma unroll
    for (int h = 0; h < 4; h++)
#pragma unroll
        for (int i = 0; i < 2; i++)
            *(float4*)(bufWV + (rr0 + i) * 132 + h * 32 + c0h) =
                make_float4(wvreg[h][i][0], wvreg[h][i][1], wvreg[h][i][2], wvreg[h][i][3]);
    __syncthreads();

    // ---- stage B: out = wv @ Wo + bo, LN, residual (4 chunks of 32 k) ----
    ull acc[8][2];
#pragma unroll
    for (int i = 0; i < 8; i++) { acc[i][0] = 0ull; acc[i][1] = 0ull; }
    for (int ch = 0; ch < 4; ch++) {
        { const float4* s = (const float4*)(Wo + (size_t)32 * ch * 128);
          float4* d = (float4*)bufWo;
#pragma unroll
          for (int i = 0; i < 4; i++) d[t + 256 * i] = s[t + 256 * i]; }
        __syncthreads();
#pragma unroll
        for (int kk = 0; kk < 32; kk += 4) {
            GEMM_STEP_8x4(bufWV, r0, 32 * ch + kk, bufWo, kk, c0, acc);
        }
        __syncthreads();
    }

    float4 bo4 = *(const float4*)(bo + c0);
    float4 g4  = *(const float4*)(gamma + c0);
    float4 be4 = *(const float4*)(beta + c0);

#pragma unroll
    for (int i = 0; i < 8; i++) {
        float o[4];
        upk(acc[i][0], o[0], o[1]); upk(acc[i][1], o[2], o[3]);
        o[0] += bo4.x; o[1] += bo4.y; o[2] += bo4.z; o[3] += bo4.w;
        float s  = o[0] + o[1] + o[2] + o[3];
        float sq = o[0]*o[0] + o[1]*o[1] + o[2]*o[2] + o[3]*o[3];
#pragma unroll
        for (int off = 16; off; off >>= 1) {
            s  += __shfl_xor_sync(0xffffffffu, s, off);
            sq += __shfl_xor_sync(0xffffffffu, sq, off);
        }
        const int row = n0 + r0 + i;
        if (row < NODES) {
            float mu = s * (1.f / 128.f);
            float var = sq * (1.f / 128.f) - mu * mu;
            float rstd = rsqrtf(var + 1e-5f);
            float4 q4 = *(const float4*)(query + (size_t)row * 128 + c0);
            float4 res;
            res.x = q4.x + (o[0] - mu) * rstd * g4.x + be4.x;
            res.y = q4.y + (o[1] - mu) * rstd * g4.y + be4.y;
            res.z = q4.z + (o[2] - mu) * rstd * g4.z + be4.z;
            res.w = q4.w + (o[3] - mu) * rstd * g4.w + be4.w;
            *(float4*)(out + (size_t)row * 128 + c0) = res;
        }
    }
}

extern "C" void kernel_launch(void* const* d_in, const int* in_sizes, int n_in,
                              void* d_out, int out_size) {
    const float* query = (const float*)d_in[0];
    const float* key   = (const float*)d_in[1];
    const float* value = (const float*)d_in[2];
    const int*   midx  = (const int*)d_in[3];
    const float* Wq = (const float*)d_in[4];
    const float* bq = (const float*)d_in[5];
    const float* Wk = (const float*)d_in[6];
    // bk = d_in[7] cancels in softmax (and is zero) — unused
    const float* Wv = (const float*)d_in[8];
    const float* bv = (const float*)d_in[9];
    const float* Wo = (const float*)d_in[10];
    const float* bo = (const float*)d_in[11];
    const float* gamma = (const float*)d_in[12];
    const float* beta  = (const float*)d_in[13];
    float* out = (float*)d_out;

    const int smem1 = (4096 + 8448) * 4;   // 50,176 B
    const int smem3 = (8448 + 4608) * 4;   // 52,224 B
    cudaFuncSetAttribute(k1_kernel, cudaFuncAttributeMaxDynamicSharedMemorySize, smem1);
    cudaFuncSetAttribute(k3_kernel, cudaFuncAttributeMaxDynamicSharedMemorySize, smem3);

    const int grid14 = (NODES + 63) / 64;  // 313
    k1_kernel<<<grid14, 256, smem1>>>(query, Wq, bq, Wk);
    k2_kernel<<<NODES / 8, 256>>>(key, value, midx);
    k3_kernel<<<grid14, 256, smem3>>>(Wv, bv, Wo, bo, gamma, beta, query, out);
}

// round 12
// speedup vs baseline: 1.0611x; 1.0046x over previous
#include <cuda_runtime.h>
#include <math.h>

#define NODES 20000

typedef unsigned long long ull;

__device__ float g_qkt[(size_t)NODES * 512];
__device__ float g_u[(size_t)NODES * 512];

__device__ __forceinline__ ull pk2(float x) {
    unsigned xi = __float_as_uint(x);
    ull r;
    asm("mov.b64 %0, {%1, %1};" : "=l"(r) : "r"(xi), "r"(xi));
    return r;
}
__device__ __forceinline__ ull ffma2(ull a, ull b, ull c) {
    ull d;
    asm("fma.rn.f32x2 %0, %1, %2, %3;" : "=l"(d) : "l"(a), "l"(b), "l"(c));
    return d;
}
__device__ __forceinline__ void upk(ull v, float& lo, float& hi) {
    unsigned a, b;
    asm("mov.b64 {%0, %1}, %2;" : "=r"(a), "=r"(b) : "l"(v));
    lo = __uint_as_float(a); hi = __uint_as_float(b);
}

// 8-row x 4-col micro-kernel step over 4 k-values.
#define GEMM_STEP_8x4(bA, r0, kbase, bW, klocal, c0, acc)                              \
    {                                                                                   \
        ulonglong2 b0 = *(const ulonglong2*)((bW) + ((klocal) + 0) * 128 + (c0));       \
        ulonglong2 b1 = *(const ulonglong2*)((bW) + ((klocal) + 1) * 128 + (c0));       \
        ulonglong2 b2 = *(const ulonglong2*)((bW) + ((klocal) + 2) * 128 + (c0));       \
        ulonglong2 b3 = *(const ulonglong2*)((bW) + ((klocal) + 3) * 128 + (c0));       \
        _Pragma("unroll")                                                               \
        for (int i = 0; i < 8; i++) {                                                   \
            float4 a = *(const float4*)((bA) + ((r0) + i) * 132 + (kbase));             \
            ull A;                                                                      \
            A = pk2(a.x); acc[i][0] = ffma2(A, b0.x, acc[i][0]); acc[i][1] = ffma2(A, b0.y, acc[i][1]); \
            A = pk2(a.y); acc[i][0] = ffma2(A, b1.x, acc[i][0]); acc[i][1] = ffma2(A, b1.y, acc[i][1]); \
            A = pk2(a.z); acc[i][0] = ffma2(A, b2.x, acc[i][0]); acc[i][1] = ffma2(A, b2.y, acc[i][1]); \
            A = pk2(a.w); acc[i][0] = ffma2(A, b3.x, acc[i][0]); acc[i][1] = ffma2(A, b3.y, acc[i][1]); \
        }                                                                               \
    }

// ---------------------------------------------------------------------------
// K1: q = query@Wq + bq;  qkt[n,h,g] = scale * sum_d q[h,d] * Wk[g, h*32+d]
// 64 nodes/CTA, 8x4 tiles. 32-k weight chunks (16KB). Q aliases the consumed
// A tile. smem = 50.2KB, 3 CTAs/SM -> single wave over 313 CTAs.
// ---------------------------------------------------------------------------
__global__ __launch_bounds__(256, 3) void k1_kernel(
    const float* __restrict__ query, const float* __restrict__ Wq,
    const float* __restrict__ bq, const float* __restrict__ Wk)
{
    extern __shared__ float sm[];
    float* bufW = sm;          // 32*128 = 4096 floats (weight chunk)
    float* bufA = sm + 4096;   // 64*132 = 8448 (query tile, later Q tile)

    const int t = threadIdx.x;
    const int n0 = blockIdx.x * 64;
    const int lane = t & 31, wg = t >> 5;
    const int c0 = 4 * lane, r0 = 8 * wg;

    // load A tile (query rows, guarded)
    {
        const int r = t & 63, part = t >> 6;  // part 0..3, 32 floats each
        float* dst = bufA + r * 132 + part * 32;
        if (n0 + r < NODES) {
            const float* src = query + (size_t)(n0 + r) * 128 + part * 32;
#pragma unroll
            for (int j = 0; j < 8; j++) *(float4*)(dst + 4 * j) = *(const float4*)(src + 4 * j);
        } else {
#pragma unroll
            for (int j = 0; j < 8; j++) *(float4*)(dst + 4 * j) = make_float4(0.f, 0.f, 0.f, 0.f);
        }
    }

    // stage A: Q = A @ Wq + bq (4 chunks of 32 k)
    ull acc[8][2];
#pragma unroll
    for (int i = 0; i < 8; i++) { acc[i][0] = 0ull; acc[i][1] = 0ull; }

    for (int ch = 0; ch < 4; ch++) {
        __syncthreads();
        { const float4* s = (const float4*)(Wq + (size_t)32 * ch * 128);
          float4* d = (float4*)bufW;
#pragma unroll
          for (int i = 0; i < 4; i++) d[t + 256 * i] = s[t + 256 * i]; }
        __syncthreads();
#pragma unroll
        for (int kk = 0; kk < 32; kk += 4) {
            GEMM_STEP_8x4(bufA, r0, 32 * ch + kk, bufW, kk, c0, acc);
        }
    }

    // all stage-A reads of bufA done -> overwrite with Q (each warp its own rows)
    __syncthreads();
    {
        float4 b4 = *(const float4*)(bq + c0);
#pragma unroll
        for (int i = 0; i < 8; i++) {
            float lo0, hi0, lo1, hi1;
            upk(acc[i][0], lo0, hi0); upk(acc[i][1], lo1, hi1);
            *(float4*)(bufA + (r0 + i) * 132 + c0) =
                make_float4(lo0 + b4.x, hi0 + b4.y, lo1 + b4.z, hi1 + b4.w);
        }
    }

    // stage B: per-head qkt; Wk^T head slice [32 d][128 g] staged per head.
    const float scale = 0.17677669529663688f;  // 1/sqrt(32)
    for (int h = 0; h < 4; h++) {
        __syncthreads();
        {   // bufW[d][g] = Wk[g][h*32+d]
            const int g = t & 127, pr = t >> 7;  // pr 0..1 -> 16 d each
#pragma unroll
            for (int jj = 0; jj < 4; jj++) {
                float4 v = *(const float4*)(Wk + (size_t)g * 128 + h * 32 + pr * 16 + 4 * jj);
                bufW[(pr * 16 + 4 * jj + 0) * 128 + g] = v.x;
                bufW[(pr * 16 + 4 * jj + 1) * 128 + g] = v.y;
                bufW[(pr * 16 + 4 * jj + 2) * 128 + g] = v.z;
                bufW[(pr * 16 + 4 * jj + 3) * 128 + g] = v.w;
            }
        }
        __syncthreads();

        ull a2[8][2];
#pragma unroll
        for (int i = 0; i < 8; i++) { a2[i][0] = 0ull; a2[i][1] = 0ull; }
#pragma unroll
        for (int dd = 0; dd < 32; dd += 4) {
            GEMM_STEP_8x4(bufA, r0, h * 32 + dd, bufW, dd, c0, a2);
        }
#pragma unroll
        for (int i = 0; i < 8; i++) {
            if (n0 + r0 + i < NODES) {
                float4 o;
                upk(a2[i][0], o.x, o.y); upk(a2[i][1], o.z, o.w);
                o.x *= scale; o.y *= scale; o.z *= scale; o.w *= scale;
                *(float4*)(g_qkt + (size_t)(n0 + r0 + i) * 512 + h * 128 + c0) = o;
            }
        }
    }
}

// ---------------------------------------------------------------------------
// K2: attention core. One warp per node. Only rows s < L are read from HBM.
// mask_idx==0: reference's -1e9 on ALL positions annihilates score
// differences in fp32 -> softmax is exactly uniform 1/32. Skip key reads.
// ---------------------------------------------------------------------------
__global__ __launch_bounds__(256) void k2_kernel(
    const float* __restrict__ key, const float* __restrict__ value,
    const int* __restrict__ mask_idx)
{
    __shared__ float  sqk[8][4][128];
    __shared__ float4 sattn[8][32];

    const int w = threadIdx.x >> 5, l = threadIdx.x & 31;
    const int n = blockIdx.x * 8 + w;

    const int mi = mask_idx[n];
    const int L = (mi == 0) ? 32 : mi;

    if (mi == 0) {
        const float ua = 1.0f / 32.0f;
        sattn[w][l] = make_float4(ua, ua, ua, ua);
    } else {
        {
            const float4* qsrc = (const float4*)(g_qkt + (size_t)n * 512);
#pragma unroll
            for (int h = 0; h < 4; h++)
                *(float4*)&sqk[w][h][4 * l] = qsrc[h * 32 + l];
        }
        __syncwarp();

        float sc[4] = {-INFINITY, -INFINITY, -INFINITY, -INFINITY};
        if (l < L) {
            const float4* krow = (const float4*)(key + ((size_t)l * NODES + n) * 128);
            float s0 = 0.f, s1 = 0.f, s2 = 0.f, s3 = 0.f;
#pragma unroll 4
            for (int c = 0; c < 32; c++) {
                float4 kv = krow[c];
                float4 q0 = *(const float4*)&sqk[w][0][4 * c];
                float4 q1 = *(const float4*)&sqk[w][1][4 * c];
                float4 q2 = *(const float4*)&sqk[w][2][4 * c];
                float4 q3 = *(const float4*)&sqk[w][3][4 * c];
                s0 = fmaf(kv.x, q0.x, fmaf(kv.y, q0.y, fmaf(kv.z, q0.z, fmaf(kv.w, q0.w, s0))));
                s1 = fmaf(kv.x, q1.x, fmaf(kv.y, q1.y, fmaf(kv.z, q1.z, fmaf(kv.w, q1.w, s1))));
                s2 = fmaf(kv.x, q2.x, fmaf(kv.y, q2.y, fmaf(kv.z, q2.z, fmaf(kv.w, q2.w, s2))));
                s3 = fmaf(kv.x, q3.x, fmaf(kv.y, q3.y, fmaf(kv.z, q3.z, fmaf(kv.w, q3.w, s3))));
            }
            sc[0] = s0; sc[1] = s1; sc[2] = s2; sc[3] = s3;
        }

        float at[4];
#pragma unroll
        for (int h = 0; h < 4; h++) {
            float m = sc[h];
#pragma unroll
            for (int off = 16; off; off >>= 1)
                m = fmaxf(m, __shfl_xor_sync(0xffffffffu, m, off));
            float e = __expf(sc[h] - m);
            float ssum = e;
#pragma unroll
            for (int off = 16; off; off >>= 1)
                ssum += __shfl_xor_sync(0xffffffffu, ssum, off);
            at[h] = e / ssum;
        }
        sattn[w][l] = make_float4(at[0], at[1], at[2], at[3]);
    }
    __syncwarp();

    float u0[4] = {0,0,0,0}, u1[4] = {0,0,0,0}, u2[4] = {0,0,0,0}, u3[4] = {0,0,0,0};
    const float* vbase = value + (size_t)n * 128 + 4 * l;
    int s = 0;
    for (; s + 2 <= L; s += 2) {
        float4 a  = sattn[w][s];
        float4 a2 = sattn[w][s + 1];
        float4 v  = *(const float4*)(vbase + (size_t)s * (NODES * 128));
        float4 v2 = *(const float4*)(vbase + (size_t)(s + 1) * (NODES * 128));
        float vv[4]  = {v.x, v.y, v.z, v.w};
        float vv2[4] = {v2.x, v2.y, v2.z, v2.w};
#pragma unroll
        for (int j = 0; j < 4; j++) {
            u0[j] = fmaf(a.x, vv[j], u0[j]);  u0[j] = fmaf(a2.x, vv2[j], u0[j]);
            u1[j] = fmaf(a.y, vv[j], u1[j]);  u1[j] = fmaf(a2.y, vv2[j], u1[j]);
            u2[j] = fmaf(a.z, vv[j], u2[j]);  u2[j] = fmaf(a2.z, vv2[j], u2[j]);
            u3[j] = fmaf(a.w, vv[j], u3[j]);  u3[j] = fmaf(a2.w, vv2[j], u3[j]);
        }
    }
    if (s < L) {
        float4 a = sattn[w][s];
        float4 v = *(const float4*)(vbase + (size_t)s * (NODES * 128));
        float vv[4] = {v.x, v.y, v.z, v.w};
#pragma unroll
        for (int j = 0; j < 4; j++) {
            u0[j] = fmaf(a.x, vv[j], u0[j]);
            u1[j] = fmaf(a.y, vv[j], u1[j]);
            u2[j] = fmaf(a.z, vv[j], u2[j]);
            u3[j] = fmaf(a.w, vv[j], u3[j]);
        }
    }
    float* ub = g_u + (size_t)n * 512 + 4 * l;
    *(float4*)(ub +   0) = make_float4(u0[0], u0[1], u0[2], u0[3]);
    *(float4*)(ub + 128) = make_float4(u1[0], u1[1], u1[2], u1[3]);
    *(float4*)(ub + 256) = make_float4(u2[0], u2[1], u2[2], u2[3]);
    *(float4*)(ub + 384) = make_float4(u3[0], u3[1], u3[2], u3[3]);
}

// ---------------------------------------------------------------------------
// K3: wv = u@Wv(per-head) + bv;  out = wv@Wo + bo;  LN;  + query
// 64 nodes/CTA. Stage A holds wv in registers; bufWV aliases the dead
// bufU region; Wo chunks alias bufWs. smem peak 52.2KB -> 3 CTAs/SM.
// ---------------------------------------------------------------------------
__global__ __launch_bounds__(256, 3) void k3_kernel(
    const float* __restrict__ Wv, const float* __restrict__ bv,
    const float* __restrict__ Wo, const float* __restrict__ bo,
    const float* __restrict__ gamma, const float* __restrict__ beta,
    const float* __restrict__ query, float* __restrict__ out)
{
    extern __shared__ float sm[];
    float* bufU  = sm;                     // 64*132 = 8448 (u head-slice)
    float* bufWs = sm + 8448;              // 128*36 = 4608 (Wv head-slice)
    float* bufWV = sm;                     // stage B: wv tile (aliases bufU)
    float* bufWo = sm + 8448;              // stage B: Wo chunk [32][128] = 4096 (aliases bufWs)

    const int t = threadIdx.x;
    const int n0 = blockIdx.x * 64;
    const int lane = t & 31, wg = t >> 5;
    const int c0 = 4 * lane, r0 = 8 * wg;

    // stage A mapping: 2 rows x 4 cols per thread, per head
    const int cg = lane & 7, rg = wg * 4 + (lane >> 3);  // rg 0..31
    const int c0h = 4 * cg, rr0 = 2 * rg;

    float wvreg[4][2][4];  // [head][row][col]

    // ---- stage A: per-head wv (held in registers) ----
    for (int h = 0; h < 4; h++) {
        __syncthreads();
        {   // u head slice
            const int r = t & 63, part = t >> 6;
            float* dst = bufU + r * 132 + part * 32;
            if (n0 + r < NODES) {
                const float* src = g_u + (size_t)(n0 + r) * 512 + h * 128 + part * 32;
#pragma unroll
                for (int j = 0; j < 8; j++) *(float4*)(dst + 4 * j) = *(const float4*)(src + 4 * j);
            } else {
#pragma unroll
                for (int j = 0; j < 8; j++) *(float4*)(dst + 4 * j) = make_float4(0.f, 0.f, 0.f, 0.f);
            }
        }
        {   // Wv head slice: bufWs[f][c] = Wv[f][h*32+c], stride 36
            const int f = t & 127, qq = t >> 7;
#pragma unroll
            for (int jj = 0; jj < 4; jj++) {
                float4 v = *(const float4*)(Wv + (size_t)f * 128 + h * 32 + qq * 16 + 4 * jj);
                *(float4*)(bufWs + f * 36 + qq * 16 + 4 * jj) = v;
            }
        }
        __syncthreads();

        ull acc2[2][2];
        acc2[0][0] = acc2[0][1] = acc2[1][0] = acc2[1][1] = 0ull;
#pragma unroll 4
        for (int f = 0; f < 128; f += 4) {
            ulonglong2 b0 = *(const ulonglong2*)(bufWs + (f + 0) * 36 + c0h);
            ulonglong2 b1 = *(const ulonglong2*)(bufWs + (f + 1) * 36 + c0h);
            ulonglong2 b2 = *(const ulonglong2*)(bufWs + (f + 2) * 36 + c0h);
            ulonglong2 b3 = *(const ulonglong2*)(bufWs + (f + 3) * 36 + c0h);
#pragma unroll
            for (int i = 0; i < 2; i++) {
                float4 a = *(const float4*)(bufU + (rr0 + i) * 132 + f);
                ull A;
                A = pk2(a.x); acc2[i][0] = ffma2(A, b0.x, acc2[i][0]); acc2[i][1] = ffma2(A, b0.y, acc2[i][1]);
                A = pk2(a.y); acc2[i][0] = ffma2(A, b1.x, acc2[i][0]); acc2[i][1] = ffma2(A, b1.y, acc2[i][1]);
                A = pk2(a.z); acc2[i][0] = ffma2(A, b2.x, acc2[i][0]); acc2[i][1] = ffma2(A, b2.y, acc2[i][1]);
                A = pk2(a.w); acc2[i][0] = ffma2(A, b3.x, acc2[i][0]); acc2[i][1] = ffma2(A, b3.y, acc2[i][1]);
            }
        }
        float4 bvv = *(const float4*)(bv + h * 32 + c0h);
#pragma unroll
        for (int i = 0; i < 2; i++) {
            upk(acc2[i][0], wvreg[h][i][0], wvreg[h][i][1]);
            upk(acc2[i][1], wvreg[h][i][2], wvreg[h][i][3]);
            wvreg[h][i][0] += bvv.x; wvreg[h][i][1] += bvv.y;
            wvreg[h][i][2] += bvv.z; wvreg[h][i][3] += bvv.w;
        }
    }

    // all bufU/bufWs reads done -> write wv tile over the aliased region
    __syncthreads();
#pragma unroll
    for (int h = 0; h < 4; h++)
#pragma unroll
        for (int i = 0; i < 2; i++)
            *(float4*)(bufWV + (rr0 + i) * 132 + h * 32 + c0h) =
                make_float4(wvreg[h][i][0], wvreg[h][i][1], wvreg[h][i][2], wvreg[h][i][3]);
    __syncthreads();

    // ---- stage B: out = wv @ Wo + bo, LN, residual (4 chunks of 32 k) ----
    ull acc[8][2];
#pragma unroll
    for (int i = 0; i < 8; i++) { acc[i][0] = 0ull; acc[i][1] = 0ull; }
    for (int ch = 0; ch < 4; ch++) {
        { const float4* s = (const float4*)(Wo + (size_t)32 * ch * 128);
          float4* d = (float4*)bufWo;
#pragma unroll
          for (int i = 0; i < 4; i++) d[t + 256 * i] = s[t + 256 * i]; }
        __syncthreads();
#pragma unroll
        for (int kk = 0; kk < 32; kk += 4) {
            GEMM_STEP_8x4(bufWV, r0, 32 * ch + kk, bufWo, kk, c0, acc);
        }
        __syncthreads();
    }

    float4 bo4 = *(const float4*)(bo + c0);
    float4 g4  = *(const float4*)(gamma + c0);
    float4 be4 = *(const float4*)(beta + c0);

#pragma unroll
    for (int i = 0; i < 8; i++) {
        float o[4];
        upk(acc[i][0], o[0], o[1]); upk(acc[i][1], o[2], o[3]);
        o[0] += bo4.x; o[1] += bo4.y; o[2] += bo4.z; o[3] += bo4.w;
        float s  = o[0] + o[1] + o[2] + o[3];
        float sq = o[0]*o[0] + o[1]*o[1] + o[2]*o[2] + o[3]*o[3];
#pragma unroll
        for (int off = 16; off; off >>= 1) {
            s  += __shfl_xor_sync(0xffffffffu, s, off);
            sq += __shfl_xor_sync(0xffffffffu, sq, off);
        }
        const int row = n0 + r0 + i;
        if (row < NODES) {
            float mu = s * (1.f / 128.f);
            float var = sq * (1.f / 128.f) - mu * mu;
            float rstd = rsqrtf(var + 1e-5f);
            float4 q4 = *(const float4*)(query + (size_t)row * 128 + c0);
            float4 res;
            res.x = q4.x + (o[0] - mu) * rstd * g4.x + be4.x;
            res.y = q4.y + (o[1] - mu) * rstd * g4.y + be4.y;
            res.z = q4.z + (o[2] - mu) * rstd * g4.z + be4.z;
            res.w = q4.w + (o[3] - mu) * rstd * g4.w + be4.w;
            *(float4*)(out + (size_t)row * 128 + c0) = res;
        }
    }
}

extern "C" void kernel_launch(void* const* d_in, const int* in_sizes, int n_in,
                              void* d_out, int out_size) {
    const float* query = (const float*)d_in[0];
    const float* key   = (const float*)d_in[1];
    const float* value = (const float*)d_in[2];
    const int*   midx  = (const int*)d_in[3];
    const float* Wq = (const float*)d_in[4];
    const float* bq = (const float*)d_in[5];
    const float* Wk = (const float*)d_in[6];
    // bk = d_in[7] cancels in softmax (and is zero) — unused
    const float* Wv = (const float*)d_in[8];
    const float* bv = (const float*)d_in[9];
    const float* Wo = (const float*)d_in[10];
    const float* bo = (const float*)d_in[11];
    const float* gamma = (const float*)d_in[12];
    const float* beta  = (const float*)d_in[13];
    float* out = (float*)d_out;

    const int smem1 = (4096 + 8448) * 4;   // 50,176 B
    const int smem3 = (8448 + 4608) * 4;   // 52,224 B
    cudaFuncSetAttribute(k1_kernel, cudaFuncAttributeMaxDynamicSharedMemorySize, smem1);
    cudaFuncSetAttribute(k3_kernel, cudaFuncAttributeMaxDynamicSharedMemorySize, smem3);

    const int grid14 = (NODES + 63) / 64;  // 313
    k1_kernel<<<grid14, 256, smem1>>>(query, Wq, bq, Wk);
    k2_kernel<<<NODES / 8, 256>>>(key, value, midx);
    k3_kernel<<<grid14, 256, smem3>>>(Wv, bv, Wo, bo, gamma, beta, query, out);
}

// round 13
// speedup vs baseline: 1.1629x; 1.0959x over previous
#include <cuda_runtime.h>
#include <math.h>

#define NODES 20000

typedef unsigned long long ull;

__device__ float g_qkt[(size_t)NODES * 512];
__device__ float g_u[(size_t)NODES * 512];
__device__ float g_wkt[128 * 128];   // WkT[c][g] = Wk[g][c]

__device__ __forceinline__ ull pk2(float x) {
    unsigned xi = __float_as_uint(x);
    ull r;
    asm("mov.b64 %0, {%1, %1};" : "=l"(r) : "r"(xi), "r"(xi));
    return r;
}
__device__ __forceinline__ ull ffma2(ull a, ull b, ull c) {
    ull d;
    asm("fma.rn.f32x2 %0, %1, %2, %3;" : "=l"(d) : "l"(a), "l"(b), "l"(c));
    return d;
}
__device__ __forceinline__ void upk(ull v, float& lo, float& hi) {
    unsigned a, b;
    asm("mov.b64 {%0, %1}, %2;" : "=r"(a), "=r"(b) : "l"(v));
    lo = __uint_as_float(a); hi = __uint_as_float(b);
}

// 8 rows x 4 cols over 4 k: A from smem (warp-private rows, broadcast reads),
// B via 16B-per-lane loads from gB (global, coalesced 512B rows, L1-hot).
#define GEMM_STEP_LDGB(bA, kbase, gB, kg, c0, acc)                                     \
    {                                                                                   \
        ulonglong2 b0 = *(const ulonglong2*)((gB) + ((kg) + 0) * 128 + (c0));           \
        ulonglong2 b1 = *(const ulonglong2*)((gB) + ((kg) + 1) * 128 + (c0));           \
        ulonglong2 b2 = *(const ulonglong2*)((gB) + ((kg) + 2) * 128 + (c0));           \
        ulonglong2 b3 = *(const ulonglong2*)((gB) + ((kg) + 3) * 128 + (c0));           \
        _Pragma("unroll")                                                               \
        for (int i = 0; i < 8; i++) {                                                   \
            float4 a = *(const float4*)((bA) + i * 132 + (kbase));                      \
            ull A;                                                                      \
            A = pk2(a.x); acc[i][0] = ffma2(A, b0.x, acc[i][0]); acc[i][1] = ffma2(A, b0.y, acc[i][1]); \
            A = pk2(a.y); acc[i][0] = ffma2(A, b1.x, acc[i][0]); acc[i][1] = ffma2(A, b1.y, acc[i][1]); \
            A = pk2(a.z); acc[i][0] = ffma2(A, b2.x, acc[i][0]); acc[i][1] = ffma2(A, b2.y, acc[i][1]); \
            A = pk2(a.w); acc[i][0] = ffma2(A, b3.x, acc[i][0]); acc[i][1] = ffma2(A, b3.y, acc[i][1]); \
        }                                                                               \
    }

// ---------------------------------------------------------------------------
// K0: WkT transpose (one-shot, 64KB)
// ---------------------------------------------------------------------------
__global__ __launch_bounds__(256) void k0_transpose(const float* __restrict__ Wk)
{
    __shared__ float tile[32][33];
    const int bx = blockIdx.x & 3, by = blockIdx.x >> 2;
    const int x = threadIdx.x & 31, y = threadIdx.x >> 5;  // 32 x 8
#pragma unroll
    for (int i = 0; i < 32; i += 8)
        tile[y + i][x] = Wk[(by * 32 + y + i) * 128 + bx * 32 + x];
    __syncthreads();
#pragma unroll
    for (int i = 0; i < 32; i += 8)
        g_wkt[(bx * 32 + y + i) * 128 + by * 32 + x] = tile[x][y + i];
}

// ---------------------------------------------------------------------------
// K1: q = query@Wq + bq;  qkt[n,h,g] = scale * sum_d q[h,d] * WkT[h*32+d][g]
// 64 nodes/CTA, warp-private 8 rows. NO __syncthreads. Weights via LDG.
// ---------------------------------------------------------------------------
__global__ __launch_bounds__(256, 3) void k1_kernel(
    const float* __restrict__ query, const float* __restrict__ Wq,
    const float* __restrict__ bq)
{
    __shared__ float bufQ[64 * 132];

    const int t = threadIdx.x;
    const int n0 = blockIdx.x * 64;
    const int lane = t & 31, wg = t >> 5;
    const int c0 = 4 * lane, r0 = 8 * wg;
    float* myA = bufQ + r0 * 132;   // warp-private 8 rows

    // load this warp's 8 query rows into smem (coalesced 512B per row)
#pragma unroll
    for (int i = 0; i < 8; i++) {
        const int row = n0 + r0 + i;
        float4 v = (row < NODES) ? *(const float4*)(query + (size_t)row * 128 + c0)
                                 : make_float4(0.f, 0.f, 0.f, 0.f);
        *(float4*)(myA + i * 132 + c0) = v;
    }
    __syncwarp();

    // stage A: Q = A @ Wq + bq  (Wq streamed via LDG, L1-hot)
    ull acc[8][2];
#pragma unroll
    for (int i = 0; i < 8; i++) { acc[i][0] = 0ull; acc[i][1] = 0ull; }
#pragma unroll 4
    for (int k = 0; k < 128; k += 4) {
        GEMM_STEP_LDGB(myA, k, Wq, k, c0, acc);
    }
    __syncwarp();   // all stage-A reads of myA done before overwrite

    {
        float4 b4 = *(const float4*)(bq + c0);
#pragma unroll
        for (int i = 0; i < 8; i++) {
            float lo0, hi0, lo1, hi1;
            upk(acc[i][0], lo0, hi0); upk(acc[i][1], lo1, hi1);
            *(float4*)(myA + i * 132 + c0) =
                make_float4(lo0 + b4.x, hi0 + b4.y, lo1 + b4.z, hi1 + b4.w);
        }
    }
    __syncwarp();

    // stage B: per-head qkt (WkT via LDG)
    const float scale = 0.17677669529663688f;  // 1/sqrt(32)
#pragma unroll
    for (int h = 0; h < 4; h++) {
        ull a2[8][2];
#pragma unroll
        for (int i = 0; i < 8; i++) { a2[i][0] = 0ull; a2[i][1] = 0ull; }
#pragma unroll 4
        for (int d = 0; d < 32; d += 4) {
            GEMM_STEP_LDGB(myA, h * 32 + d, g_wkt, h * 32 + d, c0, a2);
        }
#pragma unroll
        for (int i = 0; i < 8; i++) {
            if (n0 + r0 + i < NODES) {
                float4 o;
                upk(a2[i][0], o.x, o.y); upk(a2[i][1], o.z, o.w);
                o.x *= scale; o.y *= scale; o.z *= scale; o.w *= scale;
                *(float4*)(g_qkt + (size_t)(n0 + r0 + i) * 512 + h * 128 + c0) = o;
            }
        }
    }
}

// ---------------------------------------------------------------------------
// K2: attention core. One warp per node. Only rows s < L are read from HBM.
// mask_idx==0: reference's -1e9 on ALL positions annihilates score
// differences in fp32 -> softmax is exactly uniform 1/32. Skip key reads.
// ---------------------------------------------------------------------------
__global__ __launch_bounds__(256) void k2_kernel(
    const float* __restrict__ key, const float* __restrict__ value,
    const int* __restrict__ mask_idx)
{
    __shared__ float  sqk[8][4][128];
    __shared__ float4 sattn[8][32];

    const int w = threadIdx.x >> 5, l = threadIdx.x & 31;
    const int n = blockIdx.x * 8 + w;

    const int mi = mask_idx[n];
    const int L = (mi == 0) ? 32 : mi;

    if (mi == 0) {
        const float ua = 1.0f / 32.0f;
        sattn[w][l] = make_float4(ua, ua, ua, ua);
    } else {
        {
            const float4* qsrc = (const float4*)(g_qkt + (size_t)n * 512);
#pragma unroll
            for (int h = 0; h < 4; h++)
                *(float4*)&sqk[w][h][4 * l] = qsrc[h * 32 + l];
        }
        __syncwarp();

        float sc[4] = {-INFINITY, -INFINITY, -INFINITY, -INFINITY};
        if (l < L) {
            const float4* krow = (const float4*)(key + ((size_t)l * NODES + n) * 128);
            float s0 = 0.f, s1 = 0.f, s2 = 0.f, s3 = 0.f;
#pragma unroll 4
            for (int c = 0; c < 32; c++) {
                float4 kv = krow[c];
                float4 q0 = *(const float4*)&sqk[w][0][4 * c];
                float4 q1 = *(const float4*)&sqk[w][1][4 * c];
                float4 q2 = *(const float4*)&sqk[w][2][4 * c];
                float4 q3 = *(const float4*)&sqk[w][3][4 * c];
                s0 = fmaf(kv.x, q0.x, fmaf(kv.y, q0.y, fmaf(kv.z, q0.z, fmaf(kv.w, q0.w, s0))));
                s1 = fmaf(kv.x, q1.x, fmaf(kv.y, q1.y, fmaf(kv.z, q1.z, fmaf(kv.w, q1.w, s1))));
                s2 = fmaf(kv.x, q2.x, fmaf(kv.y, q2.y, fmaf(kv.z, q2.z, fmaf(kv.w, q2.w, s2))));
                s3 = fmaf(kv.x, q3.x, fmaf(kv.y, q3.y, fmaf(kv.z, q3.z, fmaf(kv.w, q3.w, s3))));
            }
            sc[0] = s0; sc[1] = s1; sc[2] = s2; sc[3] = s3;
        }

        float at[4];
#pragma unroll
        for (int h = 0; h < 4; h++) {
            float m = sc[h];
#pragma unroll
            for (int off = 16; off; off >>= 1)
                m = fmaxf(m, __shfl_xor_sync(0xffffffffu, m, off));
            float e = __expf(sc[h] - m);
            float ssum = e;
#pragma unroll
            for (int off = 16; off; off >>= 1)
                ssum += __shfl_xor_sync(0xffffffffu, ssum, off);
            at[h] = e / ssum;
        }
        sattn[w][l] = make_float4(at[0], at[1], at[2], at[3]);
    }
    __syncwarp();

    float u0[4] = {0,0,0,0}, u1[4] = {0,0,0,0}, u2[4] = {0,0,0,0}, u3[4] = {0,0,0,0};
    const float* vbase = value + (size_t)n * 128 + 4 * l;
    int s = 0;
    for (; s + 2 <= L; s += 2) {
        float4 a  = sattn[w][s];
        float4 a2 = sattn[w][s + 1];
        float4 v  = *(const float4*)(vbase + (size_t)s * (NODES * 128));
        float4 v2 = *(const float4*)(vbase + (size_t)(s + 1) * (NODES * 128));
        float vv[4]  = {v.x, v.y, v.z, v.w};
        float vv2[4] = {v2.x, v2.y, v2.z, v2.w};
#pragma unroll
        for (int j = 0; j < 4; j++) {
            u0[j] = fmaf(a.x, vv[j], u0[j]);  u0[j] = fmaf(a2.x, vv2[j], u0[j]);
            u1[j] = fmaf(a.y, vv[j], u1[j]);  u1[j] = fmaf(a2.y, vv2[j], u1[j]);
            u2[j] = fmaf(a.z, vv[j], u2[j]);  u2[j] = fmaf(a2.z, vv2[j], u2[j]);
            u3[j] = fmaf(a.w, vv[j], u3[j]);  u3[j] = fmaf(a2.w, vv2[j], u3[j]);
        }
    }
    if (s < L) {
        float4 a = sattn[w][s];
        float4 v = *(const float4*)(vbase + (size_t)s * (NODES * 128));
        float vv[4] = {v.x, v.y, v.z, v.w};
#pragma unroll
        for (int j = 0; j < 4; j++) {
            u0[j] = fmaf(a.x, vv[j], u0[j]);
            u1[j] = fmaf(a.y, vv[j], u1[j]);
            u2[j] = fmaf(a.z, vv[j], u2[j]);
            u3[j] = fmaf(a.w, vv[j], u3[j]);
        }
    }
    float* ub = g_u + (size_t)n * 512 + 4 * l;
    *(float4*)(ub +   0) = make_float4(u0[0], u0[1], u0[2], u0[3]);
    *(float4*)(ub + 128) = make_float4(u1[0], u1[1], u1[2], u1[3]);
    *(float4*)(ub + 256) = make_float4(u2[0], u2[1], u2[2], u2[3]);
    *(float4*)(ub + 384) = make_float4(u3[0], u3[1], u3[2], u3[3]);
}

// ---------------------------------------------------------------------------
// K3: wv = u@Wv(per-head) + bv;  out = wv@Wo + bo;  LN;  + query
// 64 nodes/CTA, warp-private rows. NO __syncthreads. u from L2 via LDG,
// Wv/Wo via LDG (coalesced rows). smem = wv tile only.
// ---------------------------------------------------------------------------
__global__ __launch_bounds__(256, 3) void k3_kernel(
    const float* __restrict__ Wv, const float* __restrict__ bv,
    const float* __restrict__ Wo, const float* __restrict__ bo,
    const float* __restrict__ gamma, const float* __restrict__ beta,
    const float* __restrict__ query, float* __restrict__ out)
{
    __shared__ float bufWV[64 * 132];

    const int t = threadIdx.x;
    const int n0 = blockIdx.x * 64;
    const int lane = t & 31, wg = t >> 5;
    const int c0 = 4 * lane, r0 = 8 * wg;
    const int hoff = (c0 >> 5) * 128;   // head slice offset in u row
    float* myWV = bufWV + r0 * 132;

    // per-row clamped u pointers (tail CTA reads row 0's data; stores guarded)
    const float* uptr[8];
#pragma unroll
    for (int i = 0; i < 8; i++) {
        int row = n0 + r0 + i;
        if (row >= NODES) row = 0;
        uptr[i] = g_u + (size_t)row * 512 + hoff;
    }

    // ---- stage A: wv[r][c0..c0+3] = sum_f u[r][h,f] * Wv[f][c0..] ----
    ull acc[8][2];
#pragma unroll
    for (int i = 0; i < 8; i++) { acc[i][0] = 0ull; acc[i][1] = 0ull; }
#pragma unroll 4
    for (int f = 0; f < 128; f += 4) {
        ulonglong2 b0 = *(const ulonglong2*)(Wv + (f + 0) * 128 + c0);
        ulonglong2 b1 = *(const ulonglong2*)(Wv + (f + 1) * 128 + c0);
        ulonglong2 b2 = *(const ulonglong2*)(Wv + (f + 2) * 128 + c0);
        ulonglong2 b3 = *(const ulonglong2*)(Wv + (f + 3) * 128 + c0);
#pragma unroll
        for (int i = 0; i < 8; i++) {
            float4 a = *(const float4*)(uptr[i] + f);
            ull A;
            A = pk2(a.x); acc[i][0] = ffma2(A, b0.x, acc[i][0]); acc[i][1] = ffma2(A, b0.y, acc[i][1]);
            A = pk2(a.y); acc[i][0] = ffma2(A, b1.x, acc[i][0]); acc[i][1] = ffma2(A, b1.y, acc[i][1]);
            A = pk2(a.z); acc[i][0] = ffma2(A, b2.x, acc[i][0]); acc[i][1] = ffma2(A, b2.y, acc[i][1]);
            A = pk2(a.w); acc[i][0] = ffma2(A, b3.x, acc[i][0]); acc[i][1] = ffma2(A, b3.y, acc[i][1]);
        }
    }
    {
        float4 b4 = *(const float4*)(bv + c0);
#pragma unroll
        for (int i = 0; i < 8; i++) {
            float lo0, hi0, lo1, hi1;
            upk(acc[i][0], lo0, hi0); upk(acc[i][1], lo1, hi1);
            *(float4*)(myWV + i * 132 + c0) =
                make_float4(lo0 + b4.x, hi0 + b4.y, lo1 + b4.z, hi1 + b4.w);
        }
    }
    __syncwarp();

    // ---- stage B: out = wv @ Wo + bo (Wo via LDG), LN, residual ----
    ull acc2[8][2];
#pragma unroll
    for (int i = 0; i < 8; i++) { acc2[i][0] = 0ull; acc2[i][1] = 0ull; }
#pragma unroll 4
    for (int k = 0; k < 128; k += 4) {
        GEMM_STEP_LDGB(myWV, k, Wo, k, c0, acc2);
    }

    float4 bo4 = *(const float4*)(bo + c0);
    float4 g4  = *(const float4*)(gamma + c0);
    float4 be4 = *(const float4*)(beta + c0);

#pragma unroll
    for (int i = 0; i < 8; i++) {
        float o[4];
        upk(acc2[i][0], o[0], o[1]); upk(acc2[i][1], o[2], o[3]);
        o[0] += bo4.x; o[1] += bo4.y; o[2] += bo4.z; o[3] += bo4.w;
        float s  = o[0] + o[1] + o[2] + o[3];
        float sq = o[0]*o[0] + o[1]*o[1] + o[2]*o[2] + o[3]*o[3];
#pragma unroll
        for (int off = 16; off; off >>= 1) {
            s  += __shfl_xor_sync(0xffffffffu, s, off);
            sq += __shfl_xor_sync(0xffffffffu, sq, off);
        }
        const int row = n0 + r0 + i;
        if (row < NODES) {
            float mu = s * (1.f / 128.f);
            float var = sq * (1.f / 128.f) - mu * mu;
            float rstd = rsqrtf(var + 1e-5f);
            float4 q4 = *(const float4*)(query + (size_t)row * 128 + c0);
            float4 res;
            res.x = q4.x + (o[0] - mu) * rstd * g4.x + be4.x;
            res.y = q4.y + (o[1] - mu) * rstd * g4.y + be4.y;
            res.z = q4.z + (o[2] - mu) * rstd * g4.z + be4.z;
            res.w = q4.w + (o[3] - mu) * rstd * g4.w + be4.w;
            *(float4*)(out + (size_t)row * 128 + c0) = res;
        }
    }
}

extern "C" void kernel_launch(void* const* d_in, const int* in_sizes, int n_in,
                              void* d_out, int out_size) {
    const float* query = (const float*)d_in[0];
    const float* key   = (const float*)d_in[1];
    const float* value = (const float*)d_in[2];
    const int*   midx  = (const int*)d_in[3];
    const float* Wq = (const float*)d_in[4];
    const float* bq = (const float*)d_in[5];
    const float* Wk = (const float*)d_in[6];
    // bk = d_in[7] cancels in softmax (and is zero) — unused
    const float* Wv = (const float*)d_in[8];
    const float* bv = (const float*)d_in[9];
    const float* Wo = (const float*)d_in[10];
    const float* bo = (const float*)d_in[11];
    const float* gamma = (const float*)d_in[12];
    const float* beta  = (const float*)d_in[13];
    float* out = (float*)d_out;

    const int grid14 = (NODES + 63) / 64;  // 313
    k0_transpose<<<16, 256>>>(Wk);
    k1_kernel<<<grid14, 256>>>(query, Wq, bq);
    k2_kernel<<<NODES / 8, 256>>>(key, value, midx);
    k3_kernel<<<grid14, 256>>>(Wv, bv, Wo, bo, gamma, beta, query, out);
}